// round 8
// baseline (speedup 1.0000x reference)
#include <cuda_runtime.h>
#include <cuda_bf16.h>
#include <cstdint>
#include <math.h>

#define BATCH  4
#define SEQ    4096
#define DMODEL 1024
#define DH     64
#define NCHUNK 8
#define ATTN_BLOCKS 1152     // 4 batches * 288 (sum over 64 q-tiles of qt/8+1)

// ---------------------------------------------------------------------------
// Scratch (device globals, no allocation)
// ---------------------------------------------------------------------------
__device__ float g_qh[BATCH * SEQ * DH];
__device__ float g_kh[BATCH * SEQ * DH];
__device__ float g_vh[BATCH * SEQ * DH];
__device__ float g_po[NCHUNK][BATCH * SEQ * DH];
__device__ float g_pm[NCHUNK][BATCH * SEQ];
__device__ float g_pl[NCHUNK][BATCH * SEQ];
__device__ uint32_t g_wh[3 * 64 * 512];   // W bf16 hi, bf16x2 words [which][n][k/2]
__device__ uint32_t g_wl[3 * 64 * 512];

// ---------------------------------------------------------------------------
__device__ __forceinline__ void mma16816(float c[4], const uint32_t a[4],
                                         uint32_t b0, uint32_t b1) {
    asm volatile(
        "mma.sync.aligned.m16n8k16.row.col.f32.bf16.bf16.f32 "
        "{%0,%1,%2,%3}, {%4,%5,%6,%7}, {%8,%9}, {%0,%1,%2,%3};"
        : "+f"(c[0]), "+f"(c[1]), "+f"(c[2]), "+f"(c[3])
        : "r"(a[0]), "r"(a[1]), "r"(a[2]), "r"(a[3]), "r"(b0), "r"(b1));
}
__device__ __forceinline__ uint32_t cvt_hi(float2 f) {
    __nv_bfloat162 h = __floats2bfloat162_rn(f.x, f.y);
    return *(uint32_t*)&h;
}
__device__ __forceinline__ uint32_t cvt_lo(float2 f, uint32_t hi) {
    __nv_bfloat162 h = *(__nv_bfloat162*)&hi;
    __nv_bfloat162 l = __floats2bfloat162_rn(f.x - __low2float(h),
                                             f.y - __high2float(h));
    return *(uint32_t*)&l;
}

// FMA-pipe exp (no MUFU), for x <= ~0
__device__ __forceinline__ float fast_exp(float x) {
    x = fmaxf(x, -87.0f);
    const float L2E = 1.4426950408889634f;
    float ys = fmaf(x, L2E, 12582912.0f);
    int   n  = __float_as_int(ys) - 0x4B400000;
    float nf = ys - 12582912.0f;
    float f  = fmaf(x, L2E, -nf);
    float p  = 1.3298820e-3f;
    p = fmaf(p, f, 9.6181291e-3f);
    p = fmaf(p, f, 5.5504109e-2f);
    p = fmaf(p, f, 2.4022649e-1f);
    p = fmaf(p, f, 6.9314718e-1f);
    p = fmaf(p, f, 1.0f);
    return __int_as_float((n + 127) << 23) * p;
}

// ---------------------------------------------------------------------------
__global__ __launch_bounds__(256)
void wconv_kernel(const float* __restrict__ wq, const float* __restrict__ wk,
                  const float* __restrict__ wv)
{
    const int t = blockIdx.x * 256 + threadIdx.x;
    const int which = t >> 15;
    const int p = t & 32767;
    const float* w = (which == 0) ? wq : (which == 1) ? wk : wv;
    float2 f = *(const float2*)(w + 2 * p);
    uint32_t h = cvt_hi(f);
    g_wh[t] = h;
    g_wl[t] = cvt_lo(f, h);
}

// ---------------------------------------------------------------------------
// Projection: smem-staged HMMA, interleaved hi/lo (word pair per (r,k2)).
// Block = 64 rows x 64 n, 4 warps, K chunked by 64.
// ---------------------------------------------------------------------------
__global__ __launch_bounds__(128)
void proj_mma_kernel(const float* __restrict__ qin, const float* __restrict__ kin,
                     const float* __restrict__ vin,
                     const float* __restrict__ bq, const float* __restrict__ bk,
                     const float* __restrict__ bv)
{
    __shared__ uint32_t Xs[64 * 36 * 2];
    __shared__ uint32_t Ws[64 * 36 * 2];

    const int which = blockIdx.y;
    const float* __restrict__ x    = (which == 0) ? qin : (which == 1) ? kin : vin;
    const float* __restrict__ bias = (which == 0) ? bq  : (which == 1) ? bk  : bv;
    float* __restrict__ out        = (which == 0) ? g_qh : (which == 1) ? g_kh : g_vh;
    const uint32_t* __restrict__ wh = g_wh + which * 32768;
    const uint32_t* __restrict__ wl = g_wl + which * 32768;

    const int tid  = threadIdx.x;
    const int warp = tid >> 5;
    const int lane = tid & 31;
    const int gid  = lane >> 2;
    const int tig  = lane & 3;
    const int row0 = blockIdx.x * 64;

    float acc[8][4] = {};

    for (int kb = 0; kb < 16; kb++) {
        __syncthreads();
        #pragma unroll
        for (int it = 0; it < 8; it++) {
            const int f = it * 128 + tid;
            const int r = f >> 4;
            const int c4 = (f & 15) << 2;
            float4 v = *(const float4*)(x + (size_t)(row0 + r) * DMODEL + kb * 64 + c4);
            uint32_t h0 = cvt_hi(make_float2(v.x, v.y));
            uint32_t h1 = cvt_hi(make_float2(v.z, v.w));
            uint32_t l0 = cvt_lo(make_float2(v.x, v.y), h0);
            uint32_t l1 = cvt_lo(make_float2(v.z, v.w), h1);
            *(uint4*)&Xs[(r * 36 + (c4 >> 1)) * 2] = make_uint4(h0, l0, h1, l1);
        }
        #pragma unroll
        for (int it = 0; it < 16; it++) {
            const int f = it * 128 + tid;
            const int n = f >> 5;
            const int k2 = f & 31;
            *(uint2*)&Ws[(n * 36 + k2) * 2] =
                make_uint2(wh[n * 512 + kb * 32 + k2], wl[n * 512 + kb * 32 + k2]);
        }
        __syncthreads();

        #pragma unroll
        for (int ks = 0; ks < 4; ks++) {
            const int d2 = (ks << 3) + tig;
            const int ra = (warp << 4) + gid;
            uint32_t ah[4], al[4];
            uint2 a0 = *(uint2*)&Xs[(ra * 36 + d2) * 2];
            uint2 a1 = *(uint2*)&Xs[((ra + 8) * 36 + d2) * 2];
            uint2 a2 = *(uint2*)&Xs[(ra * 36 + d2 + 4) * 2];
            uint2 a3 = *(uint2*)&Xs[((ra + 8) * 36 + d2 + 4) * 2];
            ah[0] = a0.x; al[0] = a0.y; ah[1] = a1.x; al[1] = a1.y;
            ah[2] = a2.x; al[2] = a2.y; ah[3] = a3.x; al[3] = a3.y;
            #pragma unroll
            for (int nt = 0; nt < 8; nt++) {
                const int nr = (nt << 3) + gid;
                uint2 b0 = *(uint2*)&Ws[(nr * 36 + d2) * 2];
                uint2 b1 = *(uint2*)&Ws[(nr * 36 + d2 + 4) * 2];
                mma16816(acc[nt], ah, b0.x, b1.x);
                mma16816(acc[nt], ah, b0.y, b1.y);
                mma16816(acc[nt], al, b0.x, b1.x);
            }
        }
    }

    const int row = row0 + (warp << 4) + gid;
    #pragma unroll
    for (int nt = 0; nt < 8; nt++) {
        const int col = (nt << 3) + (tig << 1);
        const float b0 = bias[col], b1 = bias[col + 1];
        *(float2*)(out + (size_t)row * DH + col) =
            make_float2(acc[nt][0] + b0, acc[nt][1] + b1);
        *(float2*)(out + (size_t)(row + 8) * DH + col) =
            make_float2(acc[nt][2] + b0, acc[nt][3] + b1);
    }
}

// ---------------------------------------------------------------------------
// Flash attention, mma.sync, split-KV. Round-6 geometry: 64-q tiles,
// 128 threads (4 warps x 16-row strips), 512-key chunks, 1152 blocks.
// Interleaved hi/lo smem + vectorized staging (round-7 micro-wins).
// ---------------------------------------------------------------------------
__global__ __launch_bounds__(128)
void attn_kernel()
{
    __shared__ uint32_t Ks[64 * 36 * 2];    // [key][d2] hi/lo pairs
    __shared__ uint32_t Vs[64 * 36 * 2];    // [d][k2] hi/lo pairs (transposed)

    const int tid  = threadIdx.x;
    const int warp = tid >> 5;
    const int lane = tid & 31;
    const int gid  = lane >> 2;
    const int tig  = lane & 3;

    const int bgid = (ATTN_BLOCKS - 1) - blockIdx.x;
    const int bb   = bgid / 288;
    const int r    = bgid - bb * 288;
    int a = 0;
    #pragma unroll
    for (int t = 1; t < 8; t++)
        if (4 * t * (t + 1) <= r) a = t;       // octave: qt in [8a, 8a+8)
    const int rr = r - 4 * a * (a + 1);
    const int qt = 8 * a + rr / (a + 1);
    const int ch = rr - (rr / (a + 1)) * (a + 1);

    const int q0  = qt * 64;
    const int kt0 = ch * 8;
    const int kt1 = min(kt0 + 7, qt);

    const float* __restrict__ qh = g_qh + (size_t)bb * SEQ * DH;
    const float* __restrict__ kh = g_kh + (size_t)bb * SEQ * DH;
    const float* __restrict__ vh = g_vh + (size_t)bb * SEQ * DH;

    // Q fragments (hi/lo) in registers, once
    uint32_t qfh[4][4], qfl[4][4];
    const int rowA = q0 + (warp << 4) + gid;
    const int rowB = rowA + 8;
    {
        #pragma unroll
        for (int ks = 0; ks < 4; ks++) {
            const float* p0 = qh + (size_t)rowA * DH + (ks << 4) + (tig << 1);
            float2 f0 = *(const float2*)(p0);
            float2 f1 = *(const float2*)(p0 + 8 * DH);
            float2 f2 = *(const float2*)(p0 + 8);
            float2 f3 = *(const float2*)(p0 + 8 * DH + 8);
            qfh[ks][0] = cvt_hi(f0); qfl[ks][0] = cvt_lo(f0, qfh[ks][0]);
            qfh[ks][1] = cvt_hi(f1); qfl[ks][1] = cvt_lo(f1, qfh[ks][1]);
            qfh[ks][2] = cvt_hi(f2); qfl[ks][2] = cvt_lo(f2, qfh[ks][2]);
            qfh[ks][3] = cvt_hi(f3); qfl[ks][3] = cvt_lo(f3, qfh[ks][3]);
        }
    }

    float o[8][4] = {};
    float mA = -3.0e38f, mB = -3.0e38f, lA = 0.0f, lB = 0.0f;

    for (int kt = kt0; kt <= kt1; kt++) {
        const int k0 = kt * 64;
        __syncthreads();
        // stage K: 64 keys x 64 d, hi/lo interleaved, STS.128
        #pragma unroll
        for (int it = 0; it < 8; it++) {
            const int f = it * 128 + tid;
            const int rk = f >> 4;
            const int c4 = (f & 15) << 2;
            float4 v = *(const float4*)(kh + (size_t)(k0 + rk) * DH + c4);
            uint32_t h0 = cvt_hi(make_float2(v.x, v.y));
            uint32_t h1 = cvt_hi(make_float2(v.z, v.w));
            uint32_t l0 = cvt_lo(make_float2(v.x, v.y), h0);
            uint32_t l1 = cvt_lo(make_float2(v.z, v.w), h1);
            *(uint4*)&Ks[(rk * 36 + (c4 >> 1)) * 2] = make_uint4(h0, l0, h1, l1);
        }
        // stage V transposed: word (d, k2) = (V[2k2][d], V[2k2+1][d]); lane = k2
        #pragma unroll
        for (int it = 0; it < 4; it++) {
            const int f = it * 128 + tid;
            const int k2 = f & 31;
            const int dg = f >> 5;            // 0..15 over 4 iterations
            float4 v0 = *(const float4*)(vh + (size_t)(k0 + 2 * k2) * DH + 4 * dg);
            float4 v1 = *(const float4*)(vh + (size_t)(k0 + 2 * k2 + 1) * DH + 4 * dg);
            float p0[4] = {v0.x, v0.y, v0.z, v0.w};
            float p1[4] = {v1.x, v1.y, v1.z, v1.w};
            #pragma unroll
            for (int j = 0; j < 4; j++) {
                float2 pr = make_float2(p0[j], p1[j]);
                uint32_t h = cvt_hi(pr);
                uint32_t l = cvt_lo(pr, h);
                *(uint2*)&Vs[((4 * dg + j) * 36 + k2) * 2] = make_uint2(h, l);
            }
        }
        __syncthreads();

        // S = Q K^T
        float s[8][4] = {};
        #pragma unroll
        for (int ks = 0; ks < 4; ks++) {
            const int d2 = (ks << 3) + tig;
            #pragma unroll
            for (int nt = 0; nt < 8; nt++) {
                const int kr = (nt << 3) + gid;
                uint2 b0 = *(uint2*)&Ks[(kr * 36 + d2) * 2];
                uint2 b1 = *(uint2*)&Ks[(kr * 36 + d2 + 4) * 2];
                mma16816(s[nt], qfh[ks], b0.x, b1.x);
                mma16816(s[nt], qfh[ks], b0.y, b1.y);
                mma16816(s[nt], qfl[ks], b0.x, b1.x);
            }
        }

        // scale + causal mask (only the diagonal k-tile masks)
        if (kt == qt) {
            #pragma unroll
            for (int nt = 0; nt < 8; nt++) {
                const int cb = k0 + (nt << 3) + (tig << 1);
                s[nt][0] = (cb     > rowA) ? -1.0e30f : s[nt][0] * 0.125f;
                s[nt][1] = (cb + 1 > rowA) ? -1.0e30f : s[nt][1] * 0.125f;
                s[nt][2] = (cb     > rowB) ? -1.0e30f : s[nt][2] * 0.125f;
                s[nt][3] = (cb + 1 > rowB) ? -1.0e30f : s[nt][3] * 0.125f;
            }
        } else {
            #pragma unroll
            for (int nt = 0; nt < 8; nt++) {
                s[nt][0] *= 0.125f; s[nt][1] *= 0.125f;
                s[nt][2] *= 0.125f; s[nt][3] *= 0.125f;
            }
        }

        // online softmax (quad owns a row pair)
        float mxA = -3.0e38f, mxB = -3.0e38f;
        #pragma unroll
        for (int nt = 0; nt < 8; nt++) {
            mxA = fmaxf(mxA, fmaxf(s[nt][0], s[nt][1]));
            mxB = fmaxf(mxB, fmaxf(s[nt][2], s[nt][3]));
        }
        mxA = fmaxf(mxA, __shfl_xor_sync(0xffffffffu, mxA, 1));
        mxA = fmaxf(mxA, __shfl_xor_sync(0xffffffffu, mxA, 2));
        mxB = fmaxf(mxB, __shfl_xor_sync(0xffffffffu, mxB, 1));
        mxB = fmaxf(mxB, __shfl_xor_sync(0xffffffffu, mxB, 2));
        const float mnA = fmaxf(mA, mxA), mnB = fmaxf(mB, mxB);
        const float aA = fast_exp(mA - mnA), aB = fast_exp(mB - mnB);
        mA = mnA; mB = mnB;
        float sumA = 0.0f, sumB = 0.0f;
        #pragma unroll
        for (int nt = 0; nt < 8; nt++) {
            s[nt][0] = fast_exp(s[nt][0] - mnA);
            s[nt][1] = fast_exp(s[nt][1] - mnA);
            s[nt][2] = fast_exp(s[nt][2] - mnB);
            s[nt][3] = fast_exp(s[nt][3] - mnB);
            sumA += s[nt][0] + s[nt][1];
            sumB += s[nt][2] + s[nt][3];
        }
        lA = lA * aA + sumA;
        lB = lB * aB + sumB;
        #pragma unroll
        for (int nt = 0; nt < 8; nt++) {
            o[nt][0] *= aA; o[nt][1] *= aA;
            o[nt][2] *= aB; o[nt][3] *= aB;
        }

        // O += P V  (P fragments straight from S accumulators)
        #pragma unroll
        for (int kk = 0; kk < 4; kk++) {
            uint32_t ph[4], pl[4];
            float2 p0 = make_float2(s[2 * kk][0],     s[2 * kk][1]);
            float2 p1 = make_float2(s[2 * kk][2],     s[2 * kk][3]);
            float2 p2 = make_float2(s[2 * kk + 1][0], s[2 * kk + 1][1]);
            float2 p3 = make_float2(s[2 * kk + 1][2], s[2 * kk + 1][3]);
            ph[0] = cvt_hi(p0); pl[0] = cvt_lo(p0, ph[0]);
            ph[1] = cvt_hi(p1); pl[1] = cvt_lo(p1, ph[1]);
            ph[2] = cvt_hi(p2); pl[2] = cvt_lo(p2, ph[2]);
            ph[3] = cvt_hi(p3); pl[3] = cvt_lo(p3, ph[3]);
            const int k2 = (kk << 3) + tig;
            #pragma unroll
            for (int nt = 0; nt < 8; nt++) {
                const int dr = (nt << 3) + gid;
                uint2 b0 = *(uint2*)&Vs[(dr * 36 + k2) * 2];
                uint2 b1 = *(uint2*)&Vs[(dr * 36 + k2 + 4) * 2];
                mma16816(o[nt], ph, b0.x, b1.x);
                mma16816(o[nt], ph, b0.y, b1.y);
                mma16816(o[nt], pl, b0.x, b1.x);
            }
        }
    }

    // finalize partials
    lA += __shfl_xor_sync(0xffffffffu, lA, 1);
    lA += __shfl_xor_sync(0xffffffffu, lA, 2);
    lB += __shfl_xor_sync(0xffffffffu, lB, 1);
    lB += __shfl_xor_sync(0xffffffffu, lB, 2);

    const int growA = bb * SEQ + rowA;
    const int growB = bb * SEQ + rowB;
    #pragma unroll
    for (int nt = 0; nt < 8; nt++) {
        const int col = (nt << 3) + (tig << 1);
        *(float2*)&g_po[ch][(size_t)growA * DH + col] = make_float2(o[nt][0], o[nt][1]);
        *(float2*)&g_po[ch][(size_t)growB * DH + col] = make_float2(o[nt][2], o[nt][3]);
    }
    if (tig == 0) {
        g_pm[ch][growA] = mA; g_pl[ch][growA] = lA;
        g_pm[ch][growB] = mB; g_pl[ch][growB] = lB;
    }
}

// ---------------------------------------------------------------------------
__global__ __launch_bounds__(256)
void merge_kernel(float* __restrict__ out)
{
    const int t = blockIdx.x * 256 + threadIdx.x;
    const int row = t >> 4;
    const int cg  = (t & 15) << 2;
    const int q   = row & (SEQ - 1);
    const int nc  = ((q >> 6) >> 3) + 1;     // 512-key chunks

    float mstar = -3.0e38f;
    #pragma unroll 4
    for (int c = 0; c < nc; c++)
        mstar = fmaxf(mstar, g_pm[c][row]);

    float L = 0.0f;
    float4 acc = make_float4(0.f, 0.f, 0.f, 0.f);
    #pragma unroll 4
    for (int c = 0; c < nc; c++) {
        const float wgt = __expf(g_pm[c][row] - mstar);
        L += wgt * g_pl[c][row];
        float4 ov = *(const float4*)&g_po[c][(size_t)row * DH + cg];
        acc.x += wgt * ov.x; acc.y += wgt * ov.y;
        acc.z += wgt * ov.z; acc.w += wgt * ov.w;
    }
    const float inv = 1.0f / L;
    *(float4*)(out + (size_t)row * DH + cg) =
        make_float4(acc.x * inv, acc.y * inv, acc.z * inv, acc.w * inv);
}

// ---------------------------------------------------------------------------
extern "C" void kernel_launch(void* const* d_in, const int* in_sizes, int n_in,
                              void* d_out, int out_size)
{
    (void)in_sizes; (void)n_in; (void)out_size;
    const float* q  = (const float*)d_in[0];
    const float* k  = (const float*)d_in[1];
    const float* v  = (const float*)d_in[2];
    const float* wq = (const float*)d_in[3];
    const float* bq = (const float*)d_in[4];
    const float* wk = (const float*)d_in[5];
    const float* bk = (const float*)d_in[6];
    const float* wv = (const float*)d_in[7];
    const float* bv = (const float*)d_in[8];
    float* out = (float*)d_out;

    wconv_kernel<<<384, 256>>>(wq, wk, wv);
    dim3 pgrid(BATCH * SEQ / 64, 3);   // (256, 3)
    proj_mma_kernel<<<pgrid, 128>>>(q, k, v, bq, bk, bv);
    attn_kernel<<<ATTN_BLOCKS, 128>>>();
    merge_kernel<<<BATCH * SEQ * 16 / 256, 256>>>(out);
}

// round 9
// speedup vs baseline: 1.1491x; 1.1491x over previous
#include <cuda_runtime.h>
#include <cuda_bf16.h>
#include <cstdint>
#include <math.h>

#define BATCH  4
#define SEQ    4096
#define DMODEL 1024
#define DH     64
#define NCHUNK 8
#define ATTN_BLOCKS 1152    // 4 batches * 288 (sum over qt of qt/8+1)

// ---------------------------------------------------------------------------
// Scratch (device globals, no allocation)
// ---------------------------------------------------------------------------
__device__ float g_qh[BATCH * SEQ * DH];
__device__ float g_kh[BATCH * SEQ * DH];
__device__ float g_vh[BATCH * SEQ * DH];
__device__ float g_po[NCHUNK][BATCH * SEQ * DH];
__device__ float g_pm[NCHUNK][BATCH * SEQ];
__device__ float g_pl[NCHUNK][BATCH * SEQ];
__device__ uint32_t g_wh[3 * 64 * 512];   // W bf16 hi, bf16x2 words [which][n][k/2]
__device__ uint32_t g_wl[3 * 64 * 512];
// Pre-packed K: [row][d2] bf16x2 (hi, lo separate)
__device__ uint32_t g_kph[BATCH * SEQ * 32];
__device__ uint32_t g_kpl[BATCH * SEQ * 32];
// Pre-packed V, transposed per 64-key tile: [tile][d][k2] bf16x2
__device__ uint32_t g_vph[BATCH * SEQ * 32];
__device__ uint32_t g_vpl[BATCH * SEQ * 32];

// ---------------------------------------------------------------------------
__device__ __forceinline__ void mma16816(float c[4], const uint32_t a[4],
                                         uint32_t b0, uint32_t b1) {
    asm volatile(
        "mma.sync.aligned.m16n8k16.row.col.f32.bf16.bf16.f32 "
        "{%0,%1,%2,%3}, {%4,%5,%6,%7}, {%8,%9}, {%0,%1,%2,%3};"
        : "+f"(c[0]), "+f"(c[1]), "+f"(c[2]), "+f"(c[3])
        : "r"(a[0]), "r"(a[1]), "r"(a[2]), "r"(a[3]), "r"(b0), "r"(b1));
}
__device__ __forceinline__ uint32_t cvt_hi(float2 f) {
    __nv_bfloat162 h = __floats2bfloat162_rn(f.x, f.y);
    return *(uint32_t*)&h;
}
__device__ __forceinline__ uint32_t cvt_lo(float2 f, uint32_t hi) {
    __nv_bfloat162 h = *(__nv_bfloat162*)&hi;
    __nv_bfloat162 l = __floats2bfloat162_rn(f.x - __low2float(h),
                                             f.y - __high2float(h));
    return *(uint32_t*)&l;
}

// FMA-pipe exp (no MUFU), for x <= ~0
__device__ __forceinline__ float fast_exp(float x) {
    x = fmaxf(x, -87.0f);
    const float L2E = 1.4426950408889634f;
    float ys = fmaf(x, L2E, 12582912.0f);
    int   n  = __float_as_int(ys) - 0x4B400000;
    float nf = ys - 12582912.0f;
    float f  = fmaf(x, L2E, -nf);
    float p  = 1.3298820e-3f;
    p = fmaf(p, f, 9.6181291e-3f);
    p = fmaf(p, f, 5.5504109e-2f);
    p = fmaf(p, f, 2.4022649e-1f);
    p = fmaf(p, f, 6.9314718e-1f);
    p = fmaf(p, f, 1.0f);
    return __int_as_float((n + 127) << 23) * p;
}

// ---------------------------------------------------------------------------
__global__ __launch_bounds__(256)
void wconv_kernel(const float* __restrict__ wq, const float* __restrict__ wk,
                  const float* __restrict__ wv)
{
    const int t = blockIdx.x * 256 + threadIdx.x;
    const int which = t >> 15;
    const int p = t & 32767;
    const float* w = (which == 0) ? wq : (which == 1) ? wk : wv;
    float2 f = *(const float2*)(w + 2 * p);
    uint32_t h = cvt_hi(f);
    g_wh[t] = h;
    g_wl[t] = cvt_lo(f, h);
}

// ---------------------------------------------------------------------------
// Repack K: fp32 [row][d] -> bf16x2 hi/lo words [row][d2]. Fully coalesced.
// ---------------------------------------------------------------------------
__global__ __launch_bounds__(256)
void kpack_kernel()
{
    const int t = blockIdx.x * 256 + threadIdx.x;   // 0 .. BATCH*SEQ*32-1
    float2 f = *(const float2*)(g_kh + 2 * (size_t)t);
    uint32_t h = cvt_hi(f);
    g_kph[t] = h;
    g_kpl[t] = cvt_lo(f, h);
}

// ---------------------------------------------------------------------------
// Repack V: per 64-key tile, transpose to [d][k2] bf16x2 hi/lo words.
// One block per tile (256 threads), smem staging transpose.
// ---------------------------------------------------------------------------
__global__ __launch_bounds__(256)
void vpack_kernel()
{
    __shared__ float Vt[64 * 65];   // [d][key], stride 65 (conflict-free)
    const int tile = blockIdx.x;    // 0 .. BATCH*SEQ/64-1
    const int tid = threadIdx.x;
    const float* vt = g_vh + (size_t)tile * 64 * DH;

    #pragma unroll
    for (int it = 0; it < 16; it++) {
        const int idx = it * 256 + tid;     // 0..4095
        const int key = idx >> 6;
        const int d   = idx & 63;
        Vt[d * 65 + key] = vt[(size_t)key * DH + d];
    }
    __syncthreads();

    uint32_t* oph = g_vph + (size_t)tile * 2048;
    uint32_t* opl = g_vpl + (size_t)tile * 2048;
    #pragma unroll
    for (int it = 0; it < 8; it++) {
        const int idx = it * 256 + tid;     // 0..2047
        const int d  = idx >> 5;
        const int k2 = idx & 31;
        float2 pr = make_float2(Vt[d * 65 + 2 * k2], Vt[d * 65 + 2 * k2 + 1]);
        uint32_t h = cvt_hi(pr);
        oph[idx] = h;
        opl[idx] = cvt_lo(pr, h);
    }
}

// ---------------------------------------------------------------------------
// Projection: smem-staged HMMA (round-6 exact: separate hi/lo, stride 36).
// Block = 64 rows x 64 n, 4 warps, K chunked by 64.
// ---------------------------------------------------------------------------
__global__ __launch_bounds__(128)
void proj_mma_kernel(const float* __restrict__ qin, const float* __restrict__ kin,
                     const float* __restrict__ vin,
                     const float* __restrict__ bq, const float* __restrict__ bk,
                     const float* __restrict__ bv)
{
    __shared__ uint32_t Xh[64 * 36], Xl[64 * 36];
    __shared__ uint32_t Wh[64 * 36], Wl[64 * 36];

    const int which = blockIdx.y;
    const float* __restrict__ x    = (which == 0) ? qin : (which == 1) ? kin : vin;
    const float* __restrict__ bias = (which == 0) ? bq  : (which == 1) ? bk  : bv;
    float* __restrict__ out        = (which == 0) ? g_qh : (which == 1) ? g_kh : g_vh;
    const uint32_t* __restrict__ wh = g_wh + which * 32768;
    const uint32_t* __restrict__ wl = g_wl + which * 32768;

    const int tid  = threadIdx.x;
    const int warp = tid >> 5;
    const int lane = tid & 31;
    const int gid  = lane >> 2;
    const int tig  = lane & 3;
    const int row0 = blockIdx.x * 64;

    float acc[8][4] = {};

    for (int kb = 0; kb < 16; kb++) {
        __syncthreads();
        #pragma unroll
        for (int it = 0; it < 8; it++) {
            const int f = it * 128 + tid;
            const int r = f >> 4;
            const int c4 = (f & 15) << 2;
            float4 v = *(const float4*)(x + (size_t)(row0 + r) * DMODEL + kb * 64 + c4);
            uint32_t h0 = cvt_hi(make_float2(v.x, v.y));
            uint32_t h1 = cvt_hi(make_float2(v.z, v.w));
            uint32_t l0 = cvt_lo(make_float2(v.x, v.y), h0);
            uint32_t l1 = cvt_lo(make_float2(v.z, v.w), h1);
            *(uint2*)&Xh[r * 36 + (c4 >> 1)] = make_uint2(h0, h1);
            *(uint2*)&Xl[r * 36 + (c4 >> 1)] = make_uint2(l0, l1);
        }
        #pragma unroll
        for (int it = 0; it < 16; it++) {
            const int f = it * 128 + tid;
            const int n = f >> 5;
            const int k2 = f & 31;
            Wh[n * 36 + k2] = wh[n * 512 + kb * 32 + k2];
            Wl[n * 36 + k2] = wl[n * 512 + kb * 32 + k2];
        }
        __syncthreads();

        #pragma unroll
        for (int ks = 0; ks < 4; ks++) {
            const int d2 = (ks << 3) + tig;
            const int ra = (warp << 4) + gid;
            uint32_t ah[4], al[4];
            ah[0] = Xh[ra * 36 + d2];        al[0] = Xl[ra * 36 + d2];
            ah[1] = Xh[(ra + 8) * 36 + d2];  al[1] = Xl[(ra + 8) * 36 + d2];
            ah[2] = Xh[ra * 36 + d2 + 4];    al[2] = Xl[ra * 36 + d2 + 4];
            ah[3] = Xh[(ra + 8) * 36 + d2 + 4]; al[3] = Xl[(ra + 8) * 36 + d2 + 4];
            #pragma unroll
            for (int nt = 0; nt < 8; nt++) {
                const int nr = (nt << 3) + gid;
                const uint32_t bh0 = Wh[nr * 36 + d2], bh1 = Wh[nr * 36 + d2 + 4];
                const uint32_t bl0 = Wl[nr * 36 + d2], bl1 = Wl[nr * 36 + d2 + 4];
                mma16816(acc[nt], ah, bh0, bh1);
                mma16816(acc[nt], ah, bl0, bl1);
                mma16816(acc[nt], al, bh0, bh1);
            }
        }
    }

    const int row = row0 + (warp << 4) + gid;
    #pragma unroll
    for (int nt = 0; nt < 8; nt++) {
        const int col = (nt << 3) + (tig << 1);
        const float b0 = bias[col], b1 = bias[col + 1];
        *(float2*)(out + (size_t)row * DH + col) =
            make_float2(acc[nt][0] + b0, acc[nt][1] + b1);
        *(float2*)(out + (size_t)(row + 8) * DH + col) =
            make_float2(acc[nt][2] + b0, acc[nt][3] + b1);
    }
}

// ---------------------------------------------------------------------------
// Flash attention, mma.sync, split-KV. Round-6 exact geometry: 64-q tiles,
// 128 thr (4 warps x 16-row strips), 512-key chunks, 1152 blocks, lb(128,3).
// Staging is now pure uint4 copies from pre-packed K/V (no converts/transposes).
// ---------------------------------------------------------------------------
__global__ __launch_bounds__(128, 3)
void attn_kernel()
{
    __shared__ uint32_t Ksh[64 * 36], Ksl[64 * 36];   // [key][d2]
    __shared__ uint32_t Vsh[64 * 36], Vsl[64 * 36];   // [d][k2] (transposed)

    const int tid  = threadIdx.x;
    const int warp = tid >> 5;
    const int lane = tid & 31;
    const int gid  = lane >> 2;
    const int tig  = lane & 3;

    const int bgid = (ATTN_BLOCKS - 1) - blockIdx.x;
    const int bb   = bgid / 288;
    const int r    = bgid - bb * 288;
    int a = 0;
    #pragma unroll
    for (int t = 1; t < 8; t++)
        if (4 * t * (t + 1) <= r) a = t;       // octave: qt in [8a, 8a+8)
    const int rr = r - 4 * a * (a + 1);
    const int qt = 8 * a + rr / (a + 1);
    const int ch = rr - (rr / (a + 1)) * (a + 1);

    const int q0  = qt * 64;
    const int kt0 = ch * 8;
    const int kt1 = min(kt0 + 7, qt);

    const float* __restrict__ qh = g_qh + (size_t)bb * SEQ * DH;
    const uint32_t* __restrict__ kph = g_kph + (size_t)bb * SEQ * 32;
    const uint32_t* __restrict__ kpl = g_kpl + (size_t)bb * SEQ * 32;

    // Q fragments (hi/lo) in registers, once
    uint32_t qfh[4][4], qfl[4][4];
    const int rowA = q0 + (warp << 4) + gid;
    const int rowB = rowA + 8;
    {
        #pragma unroll
        for (int ks = 0; ks < 4; ks++) {
            const float* p0 = qh + (size_t)rowA * DH + (ks << 4) + (tig << 1);
            float2 f0 = *(const float2*)(p0);
            float2 f1 = *(const float2*)(p0 + 8 * DH);
            float2 f2 = *(const float2*)(p0 + 8);
            float2 f3 = *(const float2*)(p0 + 8 * DH + 8);
            qfh[ks][0] = cvt_hi(f0); qfl[ks][0] = cvt_lo(f0, qfh[ks][0]);
            qfh[ks][1] = cvt_hi(f1); qfl[ks][1] = cvt_lo(f1, qfh[ks][1]);
            qfh[ks][2] = cvt_hi(f2); qfl[ks][2] = cvt_lo(f2, qfh[ks][2]);
            qfh[ks][3] = cvt_hi(f3); qfl[ks][3] = cvt_lo(f3, qfh[ks][3]);
        }
    }

    float o[8][4] = {};
    float mA = -3.0e38f, mB = -3.0e38f, lA = 0.0f, lB = 0.0f;

    for (int kt = kt0; kt <= kt1; kt++) {
        const int k0 = kt * 64;
        const uint32_t* vph = g_vph + ((size_t)bb * 64 + kt) * 2048;
        const uint32_t* vpl = g_vpl + ((size_t)bb * 64 + kt) * 2048;
        __syncthreads();
        // stage K: pure copy, 64 rows x 32 words, hi + lo
        #pragma unroll
        for (int it = 0; it < 4; it++) {
            const int f = it * 128 + tid;
            const int rk = f >> 3;
            const int c4 = (f & 7) << 2;
            *(uint4*)&Ksh[rk * 36 + c4] = *(const uint4*)&kph[(size_t)(k0 + rk) * 32 + c4];
            *(uint4*)&Ksl[rk * 36 + c4] = *(const uint4*)&kpl[(size_t)(k0 + rk) * 32 + c4];
        }
        // stage V: pure copy from pre-transposed tile
        #pragma unroll
        for (int it = 0; it < 4; it++) {
            const int f = it * 128 + tid;
            const int dv = f >> 3;
            const int c4 = (f & 7) << 2;
            *(uint4*)&Vsh[dv * 36 + c4] = *(const uint4*)&vph[dv * 32 + c4];
            *(uint4*)&Vsl[dv * 36 + c4] = *(const uint4*)&vpl[dv * 32 + c4];
        }
        __syncthreads();

        // S = Q K^T
        float s[8][4] = {};
        #pragma unroll
        for (int ks = 0; ks < 4; ks++) {
            const int d2 = (ks << 3) + tig;
            #pragma unroll
            for (int nt = 0; nt < 8; nt++) {
                const int kr = (nt << 3) + gid;
                const uint32_t bh0 = Ksh[kr * 36 + d2], bh1 = Ksh[kr * 36 + d2 + 4];
                const uint32_t bl0 = Ksl[kr * 36 + d2], bl1 = Ksl[kr * 36 + d2 + 4];
                mma16816(s[nt], qfh[ks], bh0, bh1);
                mma16816(s[nt], qfh[ks], bl0, bl1);
                mma16816(s[nt], qfl[ks], bh0, bh1);
            }
        }

        // scale + causal mask (only the diagonal k-tile masks)
        if (kt == qt) {
            #pragma unroll
            for (int nt = 0; nt < 8; nt++) {
                const int cb = k0 + (nt << 3) + (tig << 1);
                s[nt][0] = (cb     > rowA) ? -1.0e30f : s[nt][0] * 0.125f;
                s[nt][1] = (cb + 1 > rowA) ? -1.0e30f : s[nt][1] * 0.125f;
                s[nt][2] = (cb     > rowB) ? -1.0e30f : s[nt][2] * 0.125f;
                s[nt][3] = (cb + 1 > rowB) ? -1.0e30f : s[nt][3] * 0.125f;
            }
        } else {
            #pragma unroll
            for (int nt = 0; nt < 8; nt++) {
                s[nt][0] *= 0.125f; s[nt][1] *= 0.125f;
                s[nt][2] *= 0.125f; s[nt][3] *= 0.125f;
            }
        }

        // online softmax (quad owns a row pair)
        float mxA = -3.0e38f, mxB = -3.0e38f;
        #pragma unroll
        for (int nt = 0; nt < 8; nt++) {
            mxA = fmaxf(mxA, fmaxf(s[nt][0], s[nt][1]));
            mxB = fmaxf(mxB, fmaxf(s[nt][2], s[nt][3]));
        }
        mxA = fmaxf(mxA, __shfl_xor_sync(0xffffffffu, mxA, 1));
        mxA = fmaxf(mxA, __shfl_xor_sync(0xffffffffu, mxA, 2));
        mxB = fmaxf(mxB, __shfl_xor_sync(0xffffffffu, mxB, 1));
        mxB = fmaxf(mxB, __shfl_xor_sync(0xffffffffu, mxB, 2));
        const float mnA = fmaxf(mA, mxA), mnB = fmaxf(mB, mxB);
        const float aA = fast_exp(mA - mnA), aB = fast_exp(mB - mnB);
        mA = mnA; mB = mnB;
        float sumA = 0.0f, sumB = 0.0f;
        #pragma unroll
        for (int nt = 0; nt < 8; nt++) {
            s[nt][0] = fast_exp(s[nt][0] - mnA);
            s[nt][1] = fast_exp(s[nt][1] - mnA);
            s[nt][2] = fast_exp(s[nt][2] - mnB);
            s[nt][3] = fast_exp(s[nt][3] - mnB);
            sumA += s[nt][0] + s[nt][1];
            sumB += s[nt][2] + s[nt][3];
        }
        lA = lA * aA + sumA;
        lB = lB * aB + sumB;
        #pragma unroll
        for (int nt = 0; nt < 8; nt++) {
            o[nt][0] *= aA; o[nt][1] *= aA;
            o[nt][2] *= aB; o[nt][3] *= aB;
        }

        // O += P V  (P fragments straight from S accumulators)
        #pragma unroll
        for (int kk = 0; kk < 4; kk++) {
            uint32_t ph[4], pl[4];
            float2 p0 = make_float2(s[2 * kk][0],     s[2 * kk][1]);
            float2 p1 = make_float2(s[2 * kk][2],     s[2 * kk][3]);
            float2 p2 = make_float2(s[2 * kk + 1][0], s[2 * kk + 1][1]);
            float2 p3 = make_float2(s[2 * kk + 1][2], s[2 * kk + 1][3]);
            ph[0] = cvt_hi(p0); pl[0] = cvt_lo(p0, ph[0]);
            ph[1] = cvt_hi(p1); pl[1] = cvt_lo(p1, ph[1]);
            ph[2] = cvt_hi(p2); pl[2] = cvt_lo(p2, ph[2]);
            ph[3] = cvt_hi(p3); pl[3] = cvt_lo(p3, ph[3]);
            const int k2 = (kk << 3) + tig;
            #pragma unroll
            for (int nt = 0; nt < 8; nt++) {
                const int dr = (nt << 3) + gid;
                const uint32_t bh0 = Vsh[dr * 36 + k2], bh1 = Vsh[dr * 36 + k2 + 4];
                const uint32_t bl0 = Vsl[dr * 36 + k2], bl1 = Vsl[dr * 36 + k2 + 4];
                mma16816(o[nt], ph, bh0, bh1);
                mma16816(o[nt], ph, bl0, bl1);
                mma16816(o[nt], pl, bh0, bh1);
            }
        }
    }

    // finalize partials
    lA += __shfl_xor_sync(0xffffffffu, lA, 1);
    lA += __shfl_xor_sync(0xffffffffu, lA, 2);
    lB += __shfl_xor_sync(0xffffffffu, lB, 1);
    lB += __shfl_xor_sync(0xffffffffu, lB, 2);

    const int growA = bb * SEQ + rowA;
    const int growB = bb * SEQ + rowB;
    #pragma unroll
    for (int nt = 0; nt < 8; nt++) {
        const int col = (nt << 3) + (tig << 1);
        *(float2*)&g_po[ch][(size_t)growA * DH + col] = make_float2(o[nt][0], o[nt][1]);
        *(float2*)&g_po[ch][(size_t)growB * DH + col] = make_float2(o[nt][2], o[nt][3]);
    }
    if (tig == 0) {
        g_pm[ch][growA] = mA; g_pl[ch][growA] = lA;
        g_pm[ch][growB] = mB; g_pl[ch][growB] = lB;
    }
}

// ---------------------------------------------------------------------------
__global__ __launch_bounds__(256)
void merge_kernel(float* __restrict__ out)
{
    const int t = blockIdx.x * 256 + threadIdx.x;
    const int row = t >> 4;
    const int cg  = (t & 15) << 2;
    const int q   = row & (SEQ - 1);
    const int nc  = ((q >> 6) >> 3) + 1;     // 512-key chunks

    float mstar = -3.0e38f;
    #pragma unroll 4
    for (int c = 0; c < nc; c++)
        mstar = fmaxf(mstar, g_pm[c][row]);

    float L = 0.0f;
    float4 acc = make_float4(0.f, 0.f, 0.f, 0.f);
    #pragma unroll 4
    for (int c = 0; c < nc; c++) {
        const float wgt = __expf(g_pm[c][row] - mstar);
        L += wgt * g_pl[c][row];
        float4 ov = *(const float4*)&g_po[c][(size_t)row * DH + cg];
        acc.x += wgt * ov.x; acc.y += wgt * ov.y;
        acc.z += wgt * ov.z; acc.w += wgt * ov.w;
    }
    const float inv = 1.0f / L;
    *(float4*)(out + (size_t)row * DH + cg) =
        make_float4(acc.x * inv, acc.y * inv, acc.z * inv, acc.w * inv);
}

// ---------------------------------------------------------------------------
extern "C" void kernel_launch(void* const* d_in, const int* in_sizes, int n_in,
                              void* d_out, int out_size)
{
    (void)in_sizes; (void)n_in; (void)out_size;
    const float* q  = (const float*)d_in[0];
    const float* k  = (const float*)d_in[1];
    const float* v  = (const float*)d_in[2];
    const float* wq = (const float*)d_in[3];
    const float* bq = (const float*)d_in[4];
    const float* wk = (const float*)d_in[5];
    const float* bk = (const float*)d_in[6];
    const float* wv = (const float*)d_in[7];
    const float* bv = (const float*)d_in[8];
    float* out = (float*)d_out;

    wconv_kernel<<<384, 256>>>(wq, wk, wv);
    dim3 pgrid(BATCH * SEQ / 64, 3);   // (256, 3)
    proj_mma_kernel<<<pgrid, 128>>>(q, k, v, bq, bk, bv);
    kpack_kernel<<<BATCH * SEQ * 32 / 256, 256>>>();
    vpack_kernel<<<BATCH * SEQ / 64, 256>>>();
    attn_kernel<<<ATTN_BLOCKS, 128>>>();
    merge_kernel<<<BATCH * SEQ * 16 / 256, 256>>>(out);
}

// round 10
// speedup vs baseline: 1.1579x; 1.0077x over previous
#include <cuda_runtime.h>
#include <cuda_bf16.h>
#include <cstdint>
#include <math.h>

#define BATCH  4
#define SEQ    4096
#define DMODEL 1024
#define DH     64
#define NCHUNK 8
#define ATTN_BLOCKS 1152    // 4 batches * 288 (sum over qt of qt/8+1)

// ---------------------------------------------------------------------------
// Scratch (device globals, no allocation)
// ---------------------------------------------------------------------------
__device__ float g_qh[BATCH * SEQ * DH];
__device__ float g_kh[BATCH * SEQ * DH];
__device__ float g_vh[BATCH * SEQ * DH];
__device__ float g_po[NCHUNK][BATCH * SEQ * DH];
__device__ float g_pm[NCHUNK][BATCH * SEQ];
__device__ float g_pl[NCHUNK][BATCH * SEQ];
__device__ uint32_t g_wh[3 * 64 * 512];   // W bf16 hi, bf16x2 words [which][n][k/2]
__device__ uint32_t g_wl[3 * 64 * 512];
// Pre-packed K: per row 16 uint4, entry e=(ks*4+tig) = {h(d2),h(d2+4),l(d2),l(d2+4)}
__device__ uint4 g_kp4[BATCH * SEQ * 16];
// Pre-packed V, transposed per 64-key tile: [tile][d][e] same quad structure over k2
__device__ uint4 g_vp4[BATCH * SEQ * 16];

// ---------------------------------------------------------------------------
__device__ __forceinline__ void mma16816(float c[4], const uint32_t a[4],
                                         uint32_t b0, uint32_t b1) {
    asm volatile(
        "mma.sync.aligned.m16n8k16.row.col.f32.bf16.bf16.f32 "
        "{%0,%1,%2,%3}, {%4,%5,%6,%7}, {%8,%9}, {%0,%1,%2,%3};"
        : "+f"(c[0]), "+f"(c[1]), "+f"(c[2]), "+f"(c[3])
        : "r"(a[0]), "r"(a[1]), "r"(a[2]), "r"(a[3]), "r"(b0), "r"(b1));
}
__device__ __forceinline__ uint32_t cvt_hi(float2 f) {
    __nv_bfloat162 h = __floats2bfloat162_rn(f.x, f.y);
    return *(uint32_t*)&h;
}
__device__ __forceinline__ uint32_t cvt_lo(float2 f, uint32_t hi) {
    __nv_bfloat162 h = *(__nv_bfloat162*)&hi;
    __nv_bfloat162 l = __floats2bfloat162_rn(f.x - __low2float(h),
                                             f.y - __high2float(h));
    return *(uint32_t*)&l;
}

// FMA-pipe exp(x) for x <= ~0 (used by alpha path sparingly)
__device__ __forceinline__ float fast_exp8(float x) {   // exp(x * 0.125)
    x = fmaxf(x, -690.0f);
    const float C = 1.4426950408889634f * 0.125f;       // log2(e)/8
    float ys = fmaf(x, C, 12582912.0f);
    int   n  = __float_as_int(ys) - 0x4B400000;
    float f  = fmaf(x, C, -(ys - 12582912.0f));
    float p  = 9.6181291e-3f;                           // degree-4 2^f
    p = fmaf(p, f, 5.5504109e-2f);
    p = fmaf(p, f, 2.4022649e-1f);
    p = fmaf(p, f, 6.9314718e-1f);
    p = fmaf(p, f, 1.0f);
    return __int_as_float((n + 127) << 23) * p;
}

// ---------------------------------------------------------------------------
__global__ __launch_bounds__(256)
void wconv_kernel(const float* __restrict__ wq, const float* __restrict__ wk,
                  const float* __restrict__ wv)
{
    const int t = blockIdx.x * 256 + threadIdx.x;
    const int which = t >> 15;
    const int p = t & 32767;
    const float* w = (which == 0) ? wq : (which == 1) ? wk : wv;
    float2 f = *(const float2*)(w + 2 * p);
    uint32_t h = cvt_hi(f);
    g_wh[t] = h;
    g_wl[t] = cvt_lo(f, h);
}

// ---------------------------------------------------------------------------
// Repack K into fragment quads: row r, entry e=(ks*4+tig):
// d2 = ks*8+tig; quad = {h(d2), h(d2+4), l(d2), l(d2+4)}
// ---------------------------------------------------------------------------
__global__ __launch_bounds__(256)
void kpack_kernel()
{
    const int t = blockIdx.x * 256 + threadIdx.x;   // 0 .. BATCH*SEQ*16-1
    const int row = t >> 4;
    const int e   = t & 15;
    const int d2  = (e >> 2) * 8 + (e & 3);
    const float* base = g_kh + (size_t)row * DH;
    float2 f0 = *(const float2*)(base + 2 * d2);
    float2 f1 = *(const float2*)(base + 2 * d2 + 8);
    uint32_t h0 = cvt_hi(f0), h1 = cvt_hi(f1);
    g_kp4[t] = make_uint4(h0, h1, cvt_lo(f0, h0), cvt_lo(f1, h1));
}

// ---------------------------------------------------------------------------
// Repack V: per 64-key tile, transpose to [d][k2] then emit fragment quads:
// entry e=(kk*4+tig): k2 = kk*8+tig; quad = {h(k2), h(k2+4), l(k2), l(k2+4)}
// where word k2 packs keys (2k2, 2k2+1) for dimension d.
// ---------------------------------------------------------------------------
__global__ __launch_bounds__(256)
void vpack_kernel()
{
    __shared__ float Vt[64 * 65];   // [d][key]
    const int tile = blockIdx.x;
    const int tid = threadIdx.x;
    const float* vt = g_vh + (size_t)tile * 64 * DH;

    #pragma unroll
    for (int it = 0; it < 16; it++) {
        const int idx = it * 256 + tid;
        const int key = idx >> 6;
        const int d   = idx & 63;
        Vt[d * 65 + key] = vt[(size_t)key * DH + d];
    }
    __syncthreads();

    uint4* op = g_vp4 + (size_t)tile * 1024;
    #pragma unroll
    for (int it = 0; it < 4; it++) {
        const int idx = it * 256 + tid;     // 0..1023 = d*16 + e
        const int d = idx >> 4;
        const int e = idx & 15;
        const int k2 = (e >> 2) * 8 + (e & 3);
        float2 f0 = make_float2(Vt[d * 65 + 2 * k2],     Vt[d * 65 + 2 * k2 + 1]);
        float2 f1 = make_float2(Vt[d * 65 + 2 * k2 + 8], Vt[d * 65 + 2 * k2 + 9]);
        uint32_t h0 = cvt_hi(f0), h1 = cvt_hi(f1);
        op[idx] = make_uint4(h0, h1, cvt_lo(f0, h0), cvt_lo(f1, h1));
    }
}

// ---------------------------------------------------------------------------
// Projection: unchanged from the 235us build.
// ---------------------------------------------------------------------------
__global__ __launch_bounds__(128)
void proj_mma_kernel(const float* __restrict__ qin, const float* __restrict__ kin,
                     const float* __restrict__ vin,
                     const float* __restrict__ bq, const float* __restrict__ bk,
                     const float* __restrict__ bv)
{
    __shared__ uint32_t Xh[64 * 36], Xl[64 * 36];
    __shared__ uint32_t Wh[64 * 36], Wl[64 * 36];

    const int which = blockIdx.y;
    const float* __restrict__ x    = (which == 0) ? qin : (which == 1) ? kin : vin;
    const float* __restrict__ bias = (which == 0) ? bq  : (which == 1) ? bk  : bv;
    float* __restrict__ out        = (which == 0) ? g_qh : (which == 1) ? g_kh : g_vh;
    const uint32_t* __restrict__ wh = g_wh + which * 32768;
    const uint32_t* __restrict__ wl = g_wl + which * 32768;

    const int tid  = threadIdx.x;
    const int warp = tid >> 5;
    const int lane = tid & 31;
    const int gid  = lane >> 2;
    const int tig  = lane & 3;
    const int row0 = blockIdx.x * 64;

    float acc[8][4] = {};

    for (int kb = 0; kb < 16; kb++) {
        __syncthreads();
        #pragma unroll
        for (int it = 0; it < 8; it++) {
            const int f = it * 128 + tid;
            const int r = f >> 4;
            const int c4 = (f & 15) << 2;
            float4 v = *(const float4*)(x + (size_t)(row0 + r) * DMODEL + kb * 64 + c4);
            uint32_t h0 = cvt_hi(make_float2(v.x, v.y));
            uint32_t h1 = cvt_hi(make_float2(v.z, v.w));
            uint32_t l0 = cvt_lo(make_float2(v.x, v.y), h0);
            uint32_t l1 = cvt_lo(make_float2(v.z, v.w), h1);
            *(uint2*)&Xh[r * 36 + (c4 >> 1)] = make_uint2(h0, h1);
            *(uint2*)&Xl[r * 36 + (c4 >> 1)] = make_uint2(l0, l1);
        }
        #pragma unroll
        for (int it = 0; it < 16; it++) {
            const int f = it * 128 + tid;
            const int n = f >> 5;
            const int k2 = f & 31;
            Wh[n * 36 + k2] = wh[n * 512 + kb * 32 + k2];
            Wl[n * 36 + k2] = wl[n * 512 + kb * 32 + k2];
        }
        __syncthreads();

        #pragma unroll
        for (int ks = 0; ks < 4; ks++) {
            const int d2 = (ks << 3) + tig;
            const int ra = (warp << 4) + gid;
            uint32_t ah[4], al[4];
            ah[0] = Xh[ra * 36 + d2];        al[0] = Xl[ra * 36 + d2];
            ah[1] = Xh[(ra + 8) * 36 + d2];  al[1] = Xl[(ra + 8) * 36 + d2];
            ah[2] = Xh[ra * 36 + d2 + 4];    al[2] = Xl[ra * 36 + d2 + 4];
            ah[3] = Xh[(ra + 8) * 36 + d2 + 4]; al[3] = Xl[(ra + 8) * 36 + d2 + 4];
            #pragma unroll
            for (int nt = 0; nt < 8; nt++) {
                const int nr = (nt << 3) + gid;
                const uint32_t bh0 = Wh[nr * 36 + d2], bh1 = Wh[nr * 36 + d2 + 4];
                const uint32_t bl0 = Wl[nr * 36 + d2], bl1 = Wl[nr * 36 + d2 + 4];
                mma16816(acc[nt], ah, bh0, bh1);
                mma16816(acc[nt], ah, bl0, bl1);
                mma16816(acc[nt], al, bh0, bh1);
            }
        }
    }

    const int row = row0 + (warp << 4) + gid;
    #pragma unroll
    for (int nt = 0; nt < 8; nt++) {
        const int col = (nt << 3) + (tig << 1);
        const float b0 = bias[col], b1 = bias[col + 1];
        *(float2*)(out + (size_t)row * DH + col) =
            make_float2(acc[nt][0] + b0, acc[nt][1] + b1);
        *(float2*)(out + (size_t)(row + 8) * DH + col) =
            make_float2(acc[nt][2] + b0, acc[nt][3] + b1);
    }
}

// ---------------------------------------------------------------------------
// Flash attention, mma.sync, split-KV. 64-q tiles, 128 thr, lb(128,3).
// Fragment quads: one LDS.128 per (ks,nt) B-fragment. Scale folded into exp.
// ---------------------------------------------------------------------------
__global__ __launch_bounds__(128, 3)
void attn_kernel()
{
    __shared__ uint4 Ksm[64 * 20];   // [key][e], stride 20 uint4 (conflict-free)
    __shared__ uint4 Vsm[64 * 20];   // [d][e]

    const int tid  = threadIdx.x;
    const int warp = tid >> 5;
    const int lane = tid & 31;
    const int gid  = lane >> 2;
    const int tig  = lane & 3;

    const int bgid = (ATTN_BLOCKS - 1) - blockIdx.x;
    const int bb   = bgid / 288;
    const int r    = bgid - bb * 288;
    int a = 0;
    #pragma unroll
    for (int t = 1; t < 8; t++)
        if (4 * t * (t + 1) <= r) a = t;       // octave: qt in [8a, 8a+8)
    const int rr = r - 4 * a * (a + 1);
    const int qt = 8 * a + rr / (a + 1);
    const int ch = rr - (rr / (a + 1)) * (a + 1);

    const int q0  = qt * 64;
    const int kt0 = ch * 8;
    const int kt1 = min(kt0 + 7, qt);

    const float* __restrict__ qh = g_qh + (size_t)bb * SEQ * DH;
    const uint4* __restrict__ kp4 = g_kp4 + (size_t)bb * SEQ * 16;

    // Q fragments (hi/lo) in registers, once
    uint32_t qfh[4][4], qfl[4][4];
    const int rowA = q0 + (warp << 4) + gid;
    const int rowB = rowA + 8;
    {
        #pragma unroll
        for (int ks = 0; ks < 4; ks++) {
            const float* p0 = qh + (size_t)rowA * DH + (ks << 4) + (tig << 1);
            float2 f0 = *(const float2*)(p0);
            float2 f1 = *(const float2*)(p0 + 8 * DH);
            float2 f2 = *(const float2*)(p0 + 8);
            float2 f3 = *(const float2*)(p0 + 8 * DH + 8);
            qfh[ks][0] = cvt_hi(f0); qfl[ks][0] = cvt_lo(f0, qfh[ks][0]);
            qfh[ks][1] = cvt_hi(f1); qfl[ks][1] = cvt_lo(f1, qfh[ks][1]);
            qfh[ks][2] = cvt_hi(f2); qfl[ks][2] = cvt_lo(f2, qfh[ks][2]);
            qfh[ks][3] = cvt_hi(f3); qfl[ks][3] = cvt_lo(f3, qfh[ks][3]);
        }
    }

    float o[8][4] = {};
    float mA = -3.0e38f, mB = -3.0e38f, lA = 0.0f, lB = 0.0f;

    for (int kt = kt0; kt <= kt1; kt++) {
        const int k0 = kt * 64;
        const uint4* vp4 = g_vp4 + ((size_t)bb * 64 + kt) * 1024;
        __syncthreads();
        // stage K + V: pure uint4 copies (8 each per thread)
        #pragma unroll
        for (int it = 0; it < 8; it++) {
            const int f = it * 128 + tid;
            const int rk = f >> 4;
            const int c  = f & 15;
            Ksm[rk * 20 + c] = kp4[(size_t)(k0 + rk) * 16 + c];
            Vsm[rk * 20 + c] = vp4[rk * 16 + c];
        }
        __syncthreads();

        // S = Q K^T  (raw, unscaled)
        float s[8][4] = {};
        #pragma unroll
        for (int ks = 0; ks < 4; ks++) {
            const int eo = (ks << 2) + tig;
            #pragma unroll
            for (int nt = 0; nt < 8; nt++) {
                uint4 kb = Ksm[((nt << 3) + gid) * 20 + eo];
                mma16816(s[nt], qfh[ks], kb.x, kb.y);
                mma16816(s[nt], qfh[ks], kb.z, kb.w);
                mma16816(s[nt], qfl[ks], kb.x, kb.y);
            }
        }

        // causal mask on raw scores (diagonal tile only)
        if (kt == qt) {
            #pragma unroll
            for (int nt = 0; nt < 8; nt++) {
                const int cb = k0 + (nt << 3) + (tig << 1);
                if (cb     > rowA) s[nt][0] = -1.0e30f;
                if (cb + 1 > rowA) s[nt][1] = -1.0e30f;
                if (cb     > rowB) s[nt][2] = -1.0e30f;
                if (cb + 1 > rowB) s[nt][3] = -1.0e30f;
            }
        }

        // online softmax on raw scores; exp folds in the 1/8 scale
        float mxA = -3.0e38f, mxB = -3.0e38f;
        #pragma unroll
        for (int nt = 0; nt < 8; nt++) {
            mxA = fmaxf(mxA, fmaxf(s[nt][0], s[nt][1]));
            mxB = fmaxf(mxB, fmaxf(s[nt][2], s[nt][3]));
        }
        mxA = fmaxf(mxA, __shfl_xor_sync(0xffffffffu, mxA, 1));
        mxA = fmaxf(mxA, __shfl_xor_sync(0xffffffffu, mxA, 2));
        mxB = fmaxf(mxB, __shfl_xor_sync(0xffffffffu, mxB, 1));
        mxB = fmaxf(mxB, __shfl_xor_sync(0xffffffffu, mxB, 2));
        const float mnA = fmaxf(mA, mxA), mnB = fmaxf(mB, mxB);
        const float aA = fast_exp8(mA - mnA), aB = fast_exp8(mB - mnB);
        mA = mnA; mB = mnB;
        float sumA = 0.0f, sumB = 0.0f;
        #pragma unroll
        for (int nt = 0; nt < 8; nt++) {
            s[nt][0] = fast_exp8(s[nt][0] - mnA);
            s[nt][1] = fast_exp8(s[nt][1] - mnA);
            s[nt][2] = fast_exp8(s[nt][2] - mnB);
            s[nt][3] = fast_exp8(s[nt][3] - mnB);
            sumA += s[nt][0] + s[nt][1];
            sumB += s[nt][2] + s[nt][3];
        }
        lA = lA * aA + sumA;
        lB = lB * aB + sumB;
        #pragma unroll
        for (int nt = 0; nt < 8; nt++) {
            o[nt][0] *= aA; o[nt][1] *= aA;
            o[nt][2] *= aB; o[nt][3] *= aB;
        }

        // O += P V  (P fragments straight from S accumulators)
        #pragma unroll
        for (int kk = 0; kk < 4; kk++) {
            uint32_t ph[4], pl[4];
            float2 p0 = make_float2(s[2 * kk][0],     s[2 * kk][1]);
            float2 p1 = make_float2(s[2 * kk][2],     s[2 * kk][3]);
            float2 p2 = make_float2(s[2 * kk + 1][0], s[2 * kk + 1][1]);
            float2 p3 = make_float2(s[2 * kk + 1][2], s[2 * kk + 1][3]);
            ph[0] = cvt_hi(p0); pl[0] = cvt_lo(p0, ph[0]);
            ph[1] = cvt_hi(p1); pl[1] = cvt_lo(p1, ph[1]);
            ph[2] = cvt_hi(p2); pl[2] = cvt_lo(p2, ph[2]);
            ph[3] = cvt_hi(p3); pl[3] = cvt_lo(p3, ph[3]);
            const int eo = (kk << 2) + tig;
            #pragma unroll
            for (int nt = 0; nt < 8; nt++) {
                uint4 vb = Vsm[((nt << 3) + gid) * 20 + eo];
                mma16816(o[nt], ph, vb.x, vb.y);
                mma16816(o[nt], ph, vb.z, vb.w);
                mma16816(o[nt], pl, vb.x, vb.y);
            }
        }
    }

    // finalize partials
    lA += __shfl_xor_sync(0xffffffffu, lA, 1);
    lA += __shfl_xor_sync(0xffffffffu, lA, 2);
    lB += __shfl_xor_sync(0xffffffffu, lB, 1);
    lB += __shfl_xor_sync(0xffffffffu, lB, 2);

    const int growA = bb * SEQ + rowA;
    const int growB = bb * SEQ + rowB;
    #pragma unroll
    for (int nt = 0; nt < 8; nt++) {
        const int col = (nt << 3) + (tig << 1);
        *(float2*)&g_po[ch][(size_t)growA * DH + col] = make_float2(o[nt][0], o[nt][1]);
        *(float2*)&g_po[ch][(size_t)growB * DH + col] = make_float2(o[nt][2], o[nt][3]);
    }
    if (tig == 0) {
        g_pm[ch][growA] = mA * 0.125f; g_pl[ch][growA] = lA;
        g_pm[ch][growB] = mB * 0.125f; g_pl[ch][growB] = lB;
    }
}

// ---------------------------------------------------------------------------
__global__ __launch_bounds__(256)
void merge_kernel(float* __restrict__ out)
{
    const int t = blockIdx.x * 256 + threadIdx.x;
    const int row = t >> 4;
    const int cg  = (t & 15) << 2;
    const int q   = row & (SEQ - 1);
    const int nc  = ((q >> 6) >> 3) + 1;     // 512-key chunks

    float mstar = -3.0e38f;
    #pragma unroll 4
    for (int c = 0; c < nc; c++)
        mstar = fmaxf(mstar, g_pm[c][row]);

    float L = 0.0f;
    float4 acc = make_float4(0.f, 0.f, 0.f, 0.f);
    #pragma unroll 4
    for (int c = 0; c < nc; c++) {
        const float wgt = __expf(g_pm[c][row] - mstar);
        L += wgt * g_pl[c][row];
        float4 ov = *(const float4*)&g_po[c][(size_t)row * DH + cg];
        acc.x += wgt * ov.x; acc.y += wgt * ov.y;
        acc.z += wgt * ov.z; acc.w += wgt * ov.w;
    }
    const float inv = 1.0f / L;
    *(float4*)(out + (size_t)row * DH + cg) =
        make_float4(acc.x * inv, acc.y * inv, acc.z * inv, acc.w * inv);
}

// ---------------------------------------------------------------------------
extern "C" void kernel_launch(void* const* d_in, const int* in_sizes, int n_in,
                              void* d_out, int out_size)
{
    (void)in_sizes; (void)n_in; (void)out_size;
    const float* q  = (const float*)d_in[0];
    const float* k  = (const float*)d_in[1];
    const float* v  = (const float*)d_in[2];
    const float* wq = (const float*)d_in[3];
    const float* bq = (const float*)d_in[4];
    const float* wk = (const float*)d_in[5];
    const float* bk = (const float*)d_in[6];
    const float* wv = (const float*)d_in[7];
    const float* bv = (const float*)d_in[8];
    float* out = (float*)d_out;

    wconv_kernel<<<384, 256>>>(wq, wk, wv);
    dim3 pgrid(BATCH * SEQ / 64, 3);   // (256, 3)
    proj_mma_kernel<<<pgrid, 128>>>(q, k, v, bq, bk, bv);
    kpack_kernel<<<BATCH * SEQ * 16 / 256, 256>>>();
    vpack_kernel<<<BATCH * SEQ / 64, 256>>>();
    attn_kernel<<<ATTN_BLOCKS, 128>>>();
    merge_kernel<<<BATCH * SEQ * 16 / 256, 256>>>(out);
}

// round 11
// speedup vs baseline: 1.1976x; 1.0343x over previous
#include <cuda_runtime.h>
#include <cuda_bf16.h>
#include <cstdint>
#include <math.h>

#define BATCH  4
#define SEQ    4096
#define DMODEL 1024
#define DH     64
#define NCHUNK 8
#define ATTN_BLOCKS 1152    // 4 batches * 288 (sum over qt of qt/8+1)

// ---------------------------------------------------------------------------
// Scratch (device globals, no allocation)
// ---------------------------------------------------------------------------
__device__ float g_qh[BATCH * SEQ * DH];
__device__ float g_kh[BATCH * SEQ * DH];
__device__ float g_vh[BATCH * SEQ * DH];
__device__ float g_po[NCHUNK][BATCH * SEQ * DH];
__device__ float g_pm[NCHUNK][BATCH * SEQ];
__device__ float g_pl[NCHUNK][BATCH * SEQ];
__device__ uint32_t g_wh[3 * 64 * 512];   // W bf16 hi, bf16x2 words [which][n][k/2]
__device__ uint32_t g_wl[3 * 64 * 512];
// Pre-packed K as tf32 quads: row r, entry e=(ks*4+tig) = {d, d+4, d+8, d+12}, d=16ks+tig
__device__ uint4 g_kp4[BATCH * SEQ * 16];
// Pre-packed V (bf16 hi/lo quads), transposed per 64-key tile — unchanged
__device__ uint4 g_vp4[BATCH * SEQ * 16];

// ---------------------------------------------------------------------------
__device__ __forceinline__ void mma16816(float c[4], const uint32_t a[4],
                                         uint32_t b0, uint32_t b1) {
    asm volatile(
        "mma.sync.aligned.m16n8k16.row.col.f32.bf16.bf16.f32 "
        "{%0,%1,%2,%3}, {%4,%5,%6,%7}, {%8,%9}, {%0,%1,%2,%3};"
        : "+f"(c[0]), "+f"(c[1]), "+f"(c[2]), "+f"(c[3])
        : "r"(a[0]), "r"(a[1]), "r"(a[2]), "r"(a[3]), "r"(b0), "r"(b1));
}
__device__ __forceinline__ void mma16888tf(float c[4], const uint32_t a[4],
                                           uint32_t b0, uint32_t b1) {
    asm volatile(
        "mma.sync.aligned.m16n8k8.row.col.f32.tf32.tf32.f32 "
        "{%0,%1,%2,%3}, {%4,%5,%6,%7}, {%8,%9}, {%0,%1,%2,%3};"
        : "+f"(c[0]), "+f"(c[1]), "+f"(c[2]), "+f"(c[3])
        : "r"(a[0]), "r"(a[1]), "r"(a[2]), "r"(a[3]), "r"(b0), "r"(b1));
}
__device__ __forceinline__ uint32_t f2tf32(float f) {
    uint32_t r;
    asm("cvt.rna.tf32.f32 %0, %1;" : "=r"(r) : "f"(f));
    return r;
}
__device__ __forceinline__ uint32_t cvt_hi(float2 f) {
    __nv_bfloat162 h = __floats2bfloat162_rn(f.x, f.y);
    return *(uint32_t*)&h;
}
__device__ __forceinline__ uint32_t cvt_lo(float2 f, uint32_t hi) {
    __nv_bfloat162 h = *(__nv_bfloat162*)&hi;
    __nv_bfloat162 l = __floats2bfloat162_rn(f.x - __low2float(h),
                                             f.y - __high2float(h));
    return *(uint32_t*)&l;
}

// FMA-pipe exp(x*0.125) for x <= ~0
__device__ __forceinline__ float fast_exp8(float x) {
    x = fmaxf(x, -690.0f);
    const float C = 1.4426950408889634f * 0.125f;
    float ys = fmaf(x, C, 12582912.0f);
    int   n  = __float_as_int(ys) - 0x4B400000;
    float f  = fmaf(x, C, -(ys - 12582912.0f));
    float p  = 9.6181291e-3f;
    p = fmaf(p, f, 5.5504109e-2f);
    p = fmaf(p, f, 2.4022649e-1f);
    p = fmaf(p, f, 6.9314718e-1f);
    p = fmaf(p, f, 1.0f);
    return __int_as_float((n + 127) << 23) * p;
}

// ---------------------------------------------------------------------------
__global__ __launch_bounds__(256)
void wconv_kernel(const float* __restrict__ wq, const float* __restrict__ wk,
                  const float* __restrict__ wv)
{
    const int t = blockIdx.x * 256 + threadIdx.x;
    const int which = t >> 15;
    const int p = t & 32767;
    const float* w = (which == 0) ? wq : (which == 1) ? wk : wv;
    float2 f = *(const float2*)(w + 2 * p);
    uint32_t h = cvt_hi(f);
    g_wh[t] = h;
    g_wl[t] = cvt_lo(f, h);
}

// ---------------------------------------------------------------------------
// Repack K into tf32 fragment quads: row r, e=(ks*4+tig), d=16ks+tig:
// quad = {tf32(K[d]), tf32(K[d+4]), tf32(K[d+8]), tf32(K[d+12])}
// ---------------------------------------------------------------------------
__global__ __launch_bounds__(256)
void kpack_kernel()
{
    const int t = blockIdx.x * 256 + threadIdx.x;   // 0 .. BATCH*SEQ*16-1
    const int row = t >> 4;
    const int e   = t & 15;
    const int d   = (e >> 2) * 16 + (e & 3);
    const float* base = g_kh + (size_t)row * DH;
    g_kp4[t] = make_uint4(f2tf32(base[d]),     f2tf32(base[d + 4]),
                          f2tf32(base[d + 8]), f2tf32(base[d + 12]));
}

// ---------------------------------------------------------------------------
// Repack V (bf16 hi/lo quads over transposed tile) — unchanged.
// ---------------------------------------------------------------------------
__global__ __launch_bounds__(256)
void vpack_kernel()
{
    __shared__ float Vt[64 * 65];   // [d][key]
    const int tile = blockIdx.x;
    const int tid = threadIdx.x;
    const float* vt = g_vh + (size_t)tile * 64 * DH;

    #pragma unroll
    for (int it = 0; it < 16; it++) {
        const int idx = it * 256 + tid;
        const int key = idx >> 6;
        const int d   = idx & 63;
        Vt[d * 65 + key] = vt[(size_t)key * DH + d];
    }
    __syncthreads();

    uint4* op = g_vp4 + (size_t)tile * 1024;
    #pragma unroll
    for (int it = 0; it < 4; it++) {
        const int idx = it * 256 + tid;     // 0..1023 = d*16 + e
        const int d = idx >> 4;
        const int e = idx & 15;
        const int k2 = (e >> 2) * 8 + (e & 3);
        float2 f0 = make_float2(Vt[d * 65 + 2 * k2],     Vt[d * 65 + 2 * k2 + 1]);
        float2 f1 = make_float2(Vt[d * 65 + 2 * k2 + 8], Vt[d * 65 + 2 * k2 + 9]);
        uint32_t h0 = cvt_hi(f0), h1 = cvt_hi(f1);
        op[idx] = make_uint4(h0, h1, cvt_lo(f0, h0), cvt_lo(f1, h1));
    }
}

// ---------------------------------------------------------------------------
// Projection: unchanged from the 233.5us build (bf16 3-split for accuracy).
// ---------------------------------------------------------------------------
__global__ __launch_bounds__(128)
void proj_mma_kernel(const float* __restrict__ qin, const float* __restrict__ kin,
                     const float* __restrict__ vin,
                     const float* __restrict__ bq, const float* __restrict__ bk,
                     const float* __restrict__ bv)
{
    __shared__ uint32_t Xh[64 * 36], Xl[64 * 36];
    __shared__ uint32_t Wh[64 * 36], Wl[64 * 36];

    const int which = blockIdx.y;
    const float* __restrict__ x    = (which == 0) ? qin : (which == 1) ? kin : vin;
    const float* __restrict__ bias = (which == 0) ? bq  : (which == 1) ? bk  : bv;
    float* __restrict__ out        = (which == 0) ? g_qh : (which == 1) ? g_kh : g_vh;
    const uint32_t* __restrict__ wh = g_wh + which * 32768;
    const uint32_t* __restrict__ wl = g_wl + which * 32768;

    const int tid  = threadIdx.x;
    const int warp = tid >> 5;
    const int lane = tid & 31;
    const int gid  = lane >> 2;
    const int tig  = lane & 3;
    const int row0 = blockIdx.x * 64;

    float acc[8][4] = {};

    for (int kb = 0; kb < 16; kb++) {
        __syncthreads();
        #pragma unroll
        for (int it = 0; it < 8; it++) {
            const int f = it * 128 + tid;
            const int r = f >> 4;
            const int c4 = (f & 15) << 2;
            float4 v = *(const float4*)(x + (size_t)(row0 + r) * DMODEL + kb * 64 + c4);
            uint32_t h0 = cvt_hi(make_float2(v.x, v.y));
            uint32_t h1 = cvt_hi(make_float2(v.z, v.w));
            uint32_t l0 = cvt_lo(make_float2(v.x, v.y), h0);
            uint32_t l1 = cvt_lo(make_float2(v.z, v.w), h1);
            *(uint2*)&Xh[r * 36 + (c4 >> 1)] = make_uint2(h0, h1);
            *(uint2*)&Xl[r * 36 + (c4 >> 1)] = make_uint2(l0, l1);
        }
        #pragma unroll
        for (int it = 0; it < 16; it++) {
            const int f = it * 128 + tid;
            const int n = f >> 5;
            const int k2 = f & 31;
            Wh[n * 36 + k2] = wh[n * 512 + kb * 32 + k2];
            Wl[n * 36 + k2] = wl[n * 512 + kb * 32 + k2];
        }
        __syncthreads();

        #pragma unroll
        for (int ks = 0; ks < 4; ks++) {
            const int d2 = (ks << 3) + tig;
            const int ra = (warp << 4) + gid;
            uint32_t ah[4], al[4];
            ah[0] = Xh[ra * 36 + d2];        al[0] = Xl[ra * 36 + d2];
            ah[1] = Xh[(ra + 8) * 36 + d2];  al[1] = Xl[(ra + 8) * 36 + d2];
            ah[2] = Xh[ra * 36 + d2 + 4];    al[2] = Xl[ra * 36 + d2 + 4];
            ah[3] = Xh[(ra + 8) * 36 + d2 + 4]; al[3] = Xl[(ra + 8) * 36 + d2 + 4];
            #pragma unroll
            for (int nt = 0; nt < 8; nt++) {
                const int nr = (nt << 3) + gid;
                const uint32_t bh0 = Wh[nr * 36 + d2], bh1 = Wh[nr * 36 + d2 + 4];
                const uint32_t bl0 = Wl[nr * 36 + d2], bl1 = Wl[nr * 36 + d2 + 4];
                mma16816(acc[nt], ah, bh0, bh1);
                mma16816(acc[nt], ah, bl0, bl1);
                mma16816(acc[nt], al, bh0, bh1);
            }
        }
    }

    const int row = row0 + (warp << 4) + gid;
    #pragma unroll
    for (int nt = 0; nt < 8; nt++) {
        const int col = (nt << 3) + (tig << 1);
        const float b0 = bias[col], b1 = bias[col + 1];
        *(float2*)(out + (size_t)row * DH + col) =
            make_float2(acc[nt][0] + b0, acc[nt][1] + b1);
        *(float2*)(out + (size_t)(row + 8) * DH + col) =
            make_float2(acc[nt][2] + b0, acc[nt][3] + b1);
    }
}

// ---------------------------------------------------------------------------
// Flash attention, split-KV. QK^T = tf32 m16n8k8 (2 MMAs per k16 chunk),
// PV = bf16 3-split (unchanged). Geometry/staging as the 233.5us build.
// ---------------------------------------------------------------------------
__global__ __launch_bounds__(128, 3)
void attn_kernel()
{
    __shared__ uint4 Ksm[64 * 20];   // [key][e] tf32 quads
    __shared__ uint4 Vsm[64 * 20];   // [d][e] bf16 hi/lo quads

    const int tid  = threadIdx.x;
    const int warp = tid >> 5;
    const int lane = tid & 31;
    const int gid  = lane >> 2;
    const int tig  = lane & 3;

    const int bgid = (ATTN_BLOCKS - 1) - blockIdx.x;
    const int bb   = bgid / 288;
    const int r    = bgid - bb * 288;
    int a = 0;
    #pragma unroll
    for (int t = 1; t < 8; t++)
        if (4 * t * (t + 1) <= r) a = t;       // octave: qt in [8a, 8a+8)
    const int rr = r - 4 * a * (a + 1);
    const int qt = 8 * a + rr / (a + 1);
    const int ch = rr - (rr / (a + 1)) * (a + 1);

    const int q0  = qt * 64;
    const int kt0 = ch * 8;
    const int kt1 = min(kt0 + 7, qt);

    const float* __restrict__ qh = g_qh + (size_t)bb * SEQ * DH;
    const uint4* __restrict__ kp4 = g_kp4 + (size_t)bb * SEQ * 16;

    // Q fragments as tf32, once: per ks, halves k=[16ks..+7] and [+8..+15]
    uint32_t qf[4][8];
    const int rowA = q0 + (warp << 4) + gid;
    const int rowB = rowA + 8;
    {
        #pragma unroll
        for (int ks = 0; ks < 4; ks++) {
            const float* pA = qh + (size_t)rowA * DH + (ks << 4) + tig;
            const float* pB = qh + (size_t)rowB * DH + (ks << 4) + tig;
            qf[ks][0] = f2tf32(pA[0]);  qf[ks][1] = f2tf32(pB[0]);
            qf[ks][2] = f2tf32(pA[4]);  qf[ks][3] = f2tf32(pB[4]);
            qf[ks][4] = f2tf32(pA[8]);  qf[ks][5] = f2tf32(pB[8]);
            qf[ks][6] = f2tf32(pA[12]); qf[ks][7] = f2tf32(pB[12]);
        }
    }

    float o[8][4] = {};
    float mA = -3.0e38f, mB = -3.0e38f, lA = 0.0f, lB = 0.0f;

    for (int kt = kt0; kt <= kt1; kt++) {
        const int k0 = kt * 64;
        const uint4* vp4 = g_vp4 + ((size_t)bb * 64 + kt) * 1024;
        __syncthreads();
        #pragma unroll
        for (int it = 0; it < 8; it++) {
            const int f = it * 128 + tid;
            const int rk = f >> 4;
            const int c  = f & 15;
            Ksm[rk * 20 + c] = kp4[(size_t)(k0 + rk) * 16 + c];
            Vsm[rk * 20 + c] = vp4[rk * 16 + c];
        }
        __syncthreads();

        // S = Q K^T (tf32, 2 MMAs per (ks,nt))
        float s[8][4] = {};
        #pragma unroll
        for (int ks = 0; ks < 4; ks++) {
            const int eo = (ks << 2) + tig;
            #pragma unroll
            for (int nt = 0; nt < 8; nt++) {
                uint4 kb = Ksm[((nt << 3) + gid) * 20 + eo];
                mma16888tf(s[nt], qf[ks],     kb.x, kb.y);
                mma16888tf(s[nt], qf[ks] + 4, kb.z, kb.w);
            }
        }

        // causal mask on raw scores (diagonal tile only)
        if (kt == qt) {
            #pragma unroll
            for (int nt = 0; nt < 8; nt++) {
                const int cb = k0 + (nt << 3) + (tig << 1);
                if (cb     > rowA) s[nt][0] = -1.0e30f;
                if (cb + 1 > rowA) s[nt][1] = -1.0e30f;
                if (cb     > rowB) s[nt][2] = -1.0e30f;
                if (cb + 1 > rowB) s[nt][3] = -1.0e30f;
            }
        }

        // online softmax on raw scores; exp folds in the 1/8 scale
        float mxA = -3.0e38f, mxB = -3.0e38f;
        #pragma unroll
        for (int nt = 0; nt < 8; nt++) {
            mxA = fmaxf(mxA, fmaxf(s[nt][0], s[nt][1]));
            mxB = fmaxf(mxB, fmaxf(s[nt][2], s[nt][3]));
        }
        mxA = fmaxf(mxA, __shfl_xor_sync(0xffffffffu, mxA, 1));
        mxA = fmaxf(mxA, __shfl_xor_sync(0xffffffffu, mxA, 2));
        mxB = fmaxf(mxB, __shfl_xor_sync(0xffffffffu, mxB, 1));
        mxB = fmaxf(mxB, __shfl_xor_sync(0xffffffffu, mxB, 2));
        const float mnA = fmaxf(mA, mxA), mnB = fmaxf(mB, mxB);
        const float aA = fast_exp8(mA - mnA), aB = fast_exp8(mB - mnB);
        mA = mnA; mB = mnB;
        float sumA = 0.0f, sumB = 0.0f;
        #pragma unroll
        for (int nt = 0; nt < 8; nt++) {
            s[nt][0] = fast_exp8(s[nt][0] - mnA);
            s[nt][1] = fast_exp8(s[nt][1] - mnA);
            s[nt][2] = fast_exp8(s[nt][2] - mnB);
            s[nt][3] = fast_exp8(s[nt][3] - mnB);
            sumA += s[nt][0] + s[nt][1];
            sumB += s[nt][2] + s[nt][3];
        }
        lA = lA * aA + sumA;
        lB = lB * aB + sumB;
        #pragma unroll
        for (int nt = 0; nt < 8; nt++) {
            o[nt][0] *= aA; o[nt][1] *= aA;
            o[nt][2] *= aB; o[nt][3] *= aB;
        }

        // O += P V (bf16 3-split; P fragments straight from S accumulators)
        #pragma unroll
        for (int kk = 0; kk < 4; kk++) {
            uint32_t ph[4], pl[4];
            float2 p0 = make_float2(s[2 * kk][0],     s[2 * kk][1]);
            float2 p1 = make_float2(s[2 * kk][2],     s[2 * kk][3]);
            float2 p2 = make_float2(s[2 * kk + 1][0], s[2 * kk + 1][1]);
            float2 p3 = make_float2(s[2 * kk + 1][2], s[2 * kk + 1][3]);
            ph[0] = cvt_hi(p0); pl[0] = cvt_lo(p0, ph[0]);
            ph[1] = cvt_hi(p1); pl[1] = cvt_lo(p1, ph[1]);
            ph[2] = cvt_hi(p2); pl[2] = cvt_lo(p2, ph[2]);
            ph[3] = cvt_hi(p3); pl[3] = cvt_lo(p3, ph[3]);
            const int eo = (kk << 2) + tig;
            #pragma unroll
            for (int nt = 0; nt < 8; nt++) {
                uint4 vb = Vsm[((nt << 3) + gid) * 20 + eo];
                mma16816(o[nt], ph, vb.x, vb.y);
                mma16816(o[nt], ph, vb.z, vb.w);
                mma16816(o[nt], pl, vb.x, vb.y);
            }
        }
    }

    // finalize partials
    lA += __shfl_xor_sync(0xffffffffu, lA, 1);
    lA += __shfl_xor_sync(0xffffffffu, lA, 2);
    lB += __shfl_xor_sync(0xffffffffu, lB, 1);
    lB += __shfl_xor_sync(0xffffffffu, lB, 2);

    const int growA = bb * SEQ + rowA;
    const int growB = bb * SEQ + rowB;
    #pragma unroll
    for (int nt = 0; nt < 8; nt++) {
        const int col = (nt << 3) + (tig << 1);
        *(float2*)&g_po[ch][(size_t)growA * DH + col] = make_float2(o[nt][0], o[nt][1]);
        *(float2*)&g_po[ch][(size_t)growB * DH + col] = make_float2(o[nt][2], o[nt][3]);
    }
    if (tig == 0) {
        g_pm[ch][growA] = mA * 0.125f; g_pl[ch][growA] = lA;
        g_pm[ch][growB] = mB * 0.125f; g_pl[ch][growB] = lB;
    }
}

// ---------------------------------------------------------------------------
__global__ __launch_bounds__(256)
void merge_kernel(float* __restrict__ out)
{
    const int t = blockIdx.x * 256 + threadIdx.x;
    const int row = t >> 4;
    const int cg  = (t & 15) << 2;
    const int q   = row & (SEQ - 1);
    const int nc  = ((q >> 6) >> 3) + 1;     // 512-key chunks

    float mstar = -3.0e38f;
    #pragma unroll 4
    for (int c = 0; c < nc; c++)
        mstar = fmaxf(mstar, g_pm[c][row]);

    float L = 0.0f;
    float4 acc = make_float4(0.f, 0.f, 0.f, 0.f);
    #pragma unroll 4
    for (int c = 0; c < nc; c++) {
        const float wgt = __expf(g_pm[c][row] - mstar);
        L += wgt * g_pl[c][row];
        float4 ov = *(const float4*)&g_po[c][(size_t)row * DH + cg];
        acc.x += wgt * ov.x; acc.y += wgt * ov.y;
        acc.z += wgt * ov.z; acc.w += wgt * ov.w;
    }
    const float inv = 1.0f / L;
    *(float4*)(out + (size_t)row * DH + cg) =
        make_float4(acc.x * inv, acc.y * inv, acc.z * inv, acc.w * inv);
}

// ---------------------------------------------------------------------------
extern "C" void kernel_launch(void* const* d_in, const int* in_sizes, int n_in,
                              void* d_out, int out_size)
{
    (void)in_sizes; (void)n_in; (void)out_size;
    const float* q  = (const float*)d_in[0];
    const float* k  = (const float*)d_in[1];
    const float* v  = (const float*)d_in[2];
    const float* wq = (const float*)d_in[3];
    const float* bq = (const float*)d_in[4];
    const float* wk = (const float*)d_in[5];
    const float* bk = (const float*)d_in[6];
    const float* wv = (const float*)d_in[7];
    const float* bv = (const float*)d_in[8];
    float* out = (float*)d_out;

    wconv_kernel<<<384, 256>>>(wq, wk, wv);
    dim3 pgrid(BATCH * SEQ / 64, 3);   // (256, 3)
    proj_mma_kernel<<<pgrid, 128>>>(q, k, v, bq, bk, bv);
    kpack_kernel<<<BATCH * SEQ * 16 / 256, 256>>>();
    vpack_kernel<<<BATCH * SEQ / 64, 256>>>();
    attn_kernel<<<ATTN_BLOCKS, 128>>>();
    merge_kernel<<<BATCH * SEQ * 16 / 256, 256>>>(out);
}

// round 12
// speedup vs baseline: 1.3303x; 1.1108x over previous
#include <cuda_runtime.h>
#include <cuda_bf16.h>
#include <cuda_fp16.h>
#include <cstdint>
#include <math.h>

#define BATCH  4
#define SEQ    4096
#define DMODEL 1024
#define DH     64
#define NCHUNK 8
#define ATTN_BLOCKS 1152    // 4 batches * 288 (sum over qt of qt/8+1)

// ---------------------------------------------------------------------------
// Scratch (device globals, no allocation)
// ---------------------------------------------------------------------------
__device__ float g_qh[BATCH * SEQ * DH];
__device__ float g_kh[BATCH * SEQ * DH];
__device__ float g_vh[BATCH * SEQ * DH];
__device__ float g_po[NCHUNK][BATCH * SEQ * DH];
__device__ float g_pm[NCHUNK][BATCH * SEQ];
__device__ float g_pl[NCHUNK][BATCH * SEQ];
__device__ uint32_t g_wh[3 * 64 * 512];   // W bf16 hi, bf16x2 words [which][n][k/2]
__device__ uint32_t g_wl[3 * 64 * 512];
// Pre-packed K as tf32 quads: row r, entry e=(ks*4+tig) = {d, d+4, d+8, d+12}, d=16ks+tig
__device__ uint4 g_kp4[BATCH * SEQ * 16];
// Pre-packed V as fp16 quads, transposed per 64-key tile: [tile][d][e], e=0..7:
// tigp=e&3, kkp=e>>2; quad = {w(8kkp+tigp), w(8kkp+tigp+4), w(8kkp+16+tigp), w(8kkp+16+tigp+4)}
// where word w(k2) = half2(V[2k2][d], V[2k2+1][d])
__device__ uint4 g_vp4[BATCH * SEQ * 8];

// ---------------------------------------------------------------------------
__device__ __forceinline__ void mma16816(float c[4], const uint32_t a[4],
                                         uint32_t b0, uint32_t b1) {
    asm volatile(
        "mma.sync.aligned.m16n8k16.row.col.f32.bf16.bf16.f32 "
        "{%0,%1,%2,%3}, {%4,%5,%6,%7}, {%8,%9}, {%0,%1,%2,%3};"
        : "+f"(c[0]), "+f"(c[1]), "+f"(c[2]), "+f"(c[3])
        : "r"(a[0]), "r"(a[1]), "r"(a[2]), "r"(a[3]), "r"(b0), "r"(b1));
}
__device__ __forceinline__ void mma16816f16(float c[4], const uint32_t a[4],
                                            uint32_t b0, uint32_t b1) {
    asm volatile(
        "mma.sync.aligned.m16n8k16.row.col.f32.f16.f16.f32 "
        "{%0,%1,%2,%3}, {%4,%5,%6,%7}, {%8,%9}, {%0,%1,%2,%3};"
        : "+f"(c[0]), "+f"(c[1]), "+f"(c[2]), "+f"(c[3])
        : "r"(a[0]), "r"(a[1]), "r"(a[2]), "r"(a[3]), "r"(b0), "r"(b1));
}
__device__ __forceinline__ void mma16888tf(float c[4], const uint32_t a[4],
                                           uint32_t b0, uint32_t b1) {
    asm volatile(
        "mma.sync.aligned.m16n8k8.row.col.f32.tf32.tf32.f32 "
        "{%0,%1,%2,%3}, {%4,%5,%6,%7}, {%8,%9}, {%0,%1,%2,%3};"
        : "+f"(c[0]), "+f"(c[1]), "+f"(c[2]), "+f"(c[3])
        : "r"(a[0]), "r"(a[1]), "r"(a[2]), "r"(a[3]), "r"(b0), "r"(b1));
}
__device__ __forceinline__ uint32_t f2tf32(float f) {
    uint32_t r;
    asm("cvt.rna.tf32.f32 %0, %1;" : "=r"(r) : "f"(f));
    return r;
}
__device__ __forceinline__ uint32_t cvt_hi(float2 f) {
    __nv_bfloat162 h = __floats2bfloat162_rn(f.x, f.y);
    return *(uint32_t*)&h;
}
__device__ __forceinline__ uint32_t cvt_lo(float2 f, uint32_t hi) {
    __nv_bfloat162 h = *(__nv_bfloat162*)&hi;
    __nv_bfloat162 l = __floats2bfloat162_rn(f.x - __low2float(h),
                                             f.y - __high2float(h));
    return *(uint32_t*)&l;
}
__device__ __forceinline__ uint32_t cvt_h2(float a, float b) {
    __half2 h = __floats2half2_rn(a, b);
    return *(uint32_t*)&h;
}

// FMA-pipe exp(x*0.125) for x <= ~0
__device__ __forceinline__ float fast_exp8(float x) {
    x = fmaxf(x, -690.0f);
    const float C = 1.4426950408889634f * 0.125f;
    float ys = fmaf(x, C, 12582912.0f);
    int   n  = __float_as_int(ys) - 0x4B400000;
    float f  = fmaf(x, C, -(ys - 12582912.0f));
    float p  = 9.6181291e-3f;
    p = fmaf(p, f, 5.5504109e-2f);
    p = fmaf(p, f, 2.4022649e-1f);
    p = fmaf(p, f, 6.9314718e-1f);
    p = fmaf(p, f, 1.0f);
    return __int_as_float((n + 127) << 23) * p;
}

// ---------------------------------------------------------------------------
__global__ __launch_bounds__(256)
void wconv_kernel(const float* __restrict__ wq, const float* __restrict__ wk,
                  const float* __restrict__ wv)
{
    const int t = blockIdx.x * 256 + threadIdx.x;
    const int which = t >> 15;
    const int p = t & 32767;
    const float* w = (which == 0) ? wq : (which == 1) ? wk : wv;
    float2 f = *(const float2*)(w + 2 * p);
    uint32_t h = cvt_hi(f);
    g_wh[t] = h;
    g_wl[t] = cvt_lo(f, h);
}

// ---------------------------------------------------------------------------
// Repack K into tf32 fragment quads (unchanged).
// ---------------------------------------------------------------------------
__global__ __launch_bounds__(256)
void kpack_kernel()
{
    const int t = blockIdx.x * 256 + threadIdx.x;   // 0 .. BATCH*SEQ*16-1
    const int row = t >> 4;
    const int e   = t & 15;
    const int d   = (e >> 2) * 16 + (e & 3);
    const float* base = g_kh + (size_t)row * DH;
    g_kp4[t] = make_uint4(f2tf32(base[d]),     f2tf32(base[d + 4]),
                          f2tf32(base[d + 8]), f2tf32(base[d + 12]));
}

// ---------------------------------------------------------------------------
// Repack V: per 64-key tile, transpose to [d][k2], fp16 dual-kk quads.
// ---------------------------------------------------------------------------
__global__ __launch_bounds__(256)
void vpack_kernel()
{
    __shared__ float Vt[64 * 65];   // [d][key]
    const int tile = blockIdx.x;
    const int tid = threadIdx.x;
    const float* vt = g_vh + (size_t)tile * 64 * DH;

    #pragma unroll
    for (int it = 0; it < 16; it++) {
        const int idx = it * 256 + tid;
        const int key = idx >> 6;
        const int d   = idx & 63;
        Vt[d * 65 + key] = vt[(size_t)key * DH + d];
    }
    __syncthreads();

    uint4* op = g_vp4 + (size_t)tile * 512;
    #pragma unroll
    for (int it = 0; it < 2; it++) {
        const int idx = it * 256 + tid;     // 0..511 = d*8 + e
        const int d = idx >> 3;
        const int e = idx & 7;
        const int tigp = e & 3;
        const int kkp  = e >> 2;
        const int k2a = 8 * kkp + tigp;         // kk = kkp
        const int k2b = 8 * kkp + 16 + tigp;    // kk = kkp + 2
        const float* row = Vt + d * 65;
        op[idx] = make_uint4(
            cvt_h2(row[2 * k2a],      row[2 * k2a + 1]),
            cvt_h2(row[2 * k2a + 8],  row[2 * k2a + 9]),
            cvt_h2(row[2 * k2b],      row[2 * k2b + 1]),
            cvt_h2(row[2 * k2b + 8],  row[2 * k2b + 9]));
    }
}

// ---------------------------------------------------------------------------
// Projection: unchanged (bf16 3-split for accuracy).
// ---------------------------------------------------------------------------
__global__ __launch_bounds__(128)
void proj_mma_kernel(const float* __restrict__ qin, const float* __restrict__ kin,
                     const float* __restrict__ vin,
                     const float* __restrict__ bq, const float* __restrict__ bk,
                     const float* __restrict__ bv)
{
    __shared__ uint32_t Xh[64 * 36], Xl[64 * 36];
    __shared__ uint32_t Wh[64 * 36], Wl[64 * 36];

    const int which = blockIdx.y;
    const float* __restrict__ x    = (which == 0) ? qin : (which == 1) ? kin : vin;
    const float* __restrict__ bias = (which == 0) ? bq  : (which == 1) ? bk  : bv;
    float* __restrict__ out        = (which == 0) ? g_qh : (which == 1) ? g_kh : g_vh;
    const uint32_t* __restrict__ wh = g_wh + which * 32768;
    const uint32_t* __restrict__ wl = g_wl + which * 32768;

    const int tid  = threadIdx.x;
    const int warp = tid >> 5;
    const int lane = tid & 31;
    const int gid  = lane >> 2;
    const int tig  = lane & 3;
    const int row0 = blockIdx.x * 64;

    float acc[8][4] = {};

    for (int kb = 0; kb < 16; kb++) {
        __syncthreads();
        #pragma unroll
        for (int it = 0; it < 8; it++) {
            const int f = it * 128 + tid;
            const int r = f >> 4;
            const int c4 = (f & 15) << 2;
            float4 v = *(const float4*)(x + (size_t)(row0 + r) * DMODEL + kb * 64 + c4);
            uint32_t h0 = cvt_hi(make_float2(v.x, v.y));
            uint32_t h1 = cvt_hi(make_float2(v.z, v.w));
            uint32_t l0 = cvt_lo(make_float2(v.x, v.y), h0);
            uint32_t l1 = cvt_lo(make_float2(v.z, v.w), h1);
            *(uint2*)&Xh[r * 36 + (c4 >> 1)] = make_uint2(h0, h1);
            *(uint2*)&Xl[r * 36 + (c4 >> 1)] = make_uint2(l0, l1);
        }
        #pragma unroll
        for (int it = 0; it < 16; it++) {
            const int f = it * 128 + tid;
            const int n = f >> 5;
            const int k2 = f & 31;
            Wh[n * 36 + k2] = wh[n * 512 + kb * 32 + k2];
            Wl[n * 36 + k2] = wl[n * 512 + kb * 32 + k2];
        }
        __syncthreads();

        #pragma unroll
        for (int ks = 0; ks < 4; ks++) {
            const int d2 = (ks << 3) + tig;
            const int ra = (warp << 4) + gid;
            uint32_t ah[4], al[4];
            ah[0] = Xh[ra * 36 + d2];        al[0] = Xl[ra * 36 + d2];
            ah[1] = Xh[(ra + 8) * 36 + d2];  al[1] = Xl[(ra + 8) * 36 + d2];
            ah[2] = Xh[ra * 36 + d2 + 4];    al[2] = Xl[ra * 36 + d2 + 4];
            ah[3] = Xh[(ra + 8) * 36 + d2 + 4]; al[3] = Xl[(ra + 8) * 36 + d2 + 4];
            #pragma unroll
            for (int nt = 0; nt < 8; nt++) {
                const int nr = (nt << 3) + gid;
                const uint32_t bh0 = Wh[nr * 36 + d2], bh1 = Wh[nr * 36 + d2 + 4];
                const uint32_t bl0 = Wl[nr * 36 + d2], bl1 = Wl[nr * 36 + d2 + 4];
                mma16816(acc[nt], ah, bh0, bh1);
                mma16816(acc[nt], ah, bl0, bl1);
                mma16816(acc[nt], al, bh0, bh1);
            }
        }
    }

    const int row = row0 + (warp << 4) + gid;
    #pragma unroll
    for (int nt = 0; nt < 8; nt++) {
        const int col = (nt << 3) + (tig << 1);
        const float b0 = bias[col], b1 = bias[col + 1];
        *(float2*)(out + (size_t)row * DH + col) =
            make_float2(acc[nt][0] + b0, acc[nt][1] + b1);
        *(float2*)(out + (size_t)(row + 8) * DH + col) =
            make_float2(acc[nt][2] + b0, acc[nt][3] + b1);
    }
}

// ---------------------------------------------------------------------------
// Flash attention, split-KV. QK^T = tf32 (64 MMAs), PV = fp16 no-split (32).
// ---------------------------------------------------------------------------
__global__ __launch_bounds__(128, 3)
void attn_kernel()
{
    __shared__ uint4 Ksm[64 * 20];   // [key][e] tf32 quads
    __shared__ uint4 Vsm[64 * 12];   // [d][e] fp16 dual-kk quads (8 used/row)

    const int tid  = threadIdx.x;
    const int warp = tid >> 5;
    const int lane = tid & 31;
    const int gid  = lane >> 2;
    const int tig  = lane & 3;

    const int bgid = (ATTN_BLOCKS - 1) - blockIdx.x;
    const int bb   = bgid / 288;
    const int r    = bgid - bb * 288;
    int a = 0;
    #pragma unroll
    for (int t = 1; t < 8; t++)
        if (4 * t * (t + 1) <= r) a = t;       // octave: qt in [8a, 8a+8)
    const int rr = r - 4 * a * (a + 1);
    const int qt = 8 * a + rr / (a + 1);
    const int ch = rr - (rr / (a + 1)) * (a + 1);

    const int q0  = qt * 64;
    const int kt0 = ch * 8;
    const int kt1 = min(kt0 + 7, qt);

    const float* __restrict__ qh = g_qh + (size_t)bb * SEQ * DH;
    const uint4* __restrict__ kp4 = g_kp4 + (size_t)bb * SEQ * 16;

    // Q fragments as tf32, once
    uint32_t qf[4][8];
    const int rowA = q0 + (warp << 4) + gid;
    const int rowB = rowA + 8;
    {
        #pragma unroll
        for (int ks = 0; ks < 4; ks++) {
            const float* pA = qh + (size_t)rowA * DH + (ks << 4) + tig;
            const float* pB = qh + (size_t)rowB * DH + (ks << 4) + tig;
            qf[ks][0] = f2tf32(pA[0]);  qf[ks][1] = f2tf32(pB[0]);
            qf[ks][2] = f2tf32(pA[4]);  qf[ks][3] = f2tf32(pB[4]);
            qf[ks][4] = f2tf32(pA[8]);  qf[ks][5] = f2tf32(pB[8]);
            qf[ks][6] = f2tf32(pA[12]); qf[ks][7] = f2tf32(pB[12]);
        }
    }

    float o[8][4] = {};
    float mA = -3.0e38f, mB = -3.0e38f, lA = 0.0f, lB = 0.0f;

    for (int kt = kt0; kt <= kt1; kt++) {
        const int k0 = kt * 64;
        const uint4* vp4 = g_vp4 + ((size_t)bb * 64 + kt) * 512;
        __syncthreads();
        // stage K (8 uint4/thread) + V (4 uint4/thread)
        #pragma unroll
        for (int it = 0; it < 8; it++) {
            const int f = it * 128 + tid;
            const int rk = f >> 4;
            const int c  = f & 15;
            Ksm[rk * 20 + c] = kp4[(size_t)(k0 + rk) * 16 + c];
        }
        #pragma unroll
        for (int it = 0; it < 4; it++) {
            const int f = it * 128 + tid;
            const int dv = f >> 3;
            const int c  = f & 7;
            Vsm[dv * 12 + c] = vp4[dv * 8 + c];
        }
        __syncthreads();

        // S = Q K^T (tf32, 2 MMAs per (ks,nt))
        float s[8][4] = {};
        #pragma unroll
        for (int ks = 0; ks < 4; ks++) {
            const int eo = (ks << 2) + tig;
            #pragma unroll
            for (int nt = 0; nt < 8; nt++) {
                uint4 kb = Ksm[((nt << 3) + gid) * 20 + eo];
                mma16888tf(s[nt], qf[ks],     kb.x, kb.y);
                mma16888tf(s[nt], qf[ks] + 4, kb.z, kb.w);
            }
        }

        // causal mask on raw scores (diagonal tile only)
        if (kt == qt) {
            #pragma unroll
            for (int nt = 0; nt < 8; nt++) {
                const int cb = k0 + (nt << 3) + (tig << 1);
                if (cb     > rowA) s[nt][0] = -1.0e30f;
                if (cb + 1 > rowA) s[nt][1] = -1.0e30f;
                if (cb     > rowB) s[nt][2] = -1.0e30f;
                if (cb + 1 > rowB) s[nt][3] = -1.0e30f;
            }
        }

        // online softmax on raw scores; exp folds in the 1/8 scale
        float mxA = -3.0e38f, mxB = -3.0e38f;
        #pragma unroll
        for (int nt = 0; nt < 8; nt++) {
            mxA = fmaxf(mxA, fmaxf(s[nt][0], s[nt][1]));
            mxB = fmaxf(mxB, fmaxf(s[nt][2], s[nt][3]));
        }
        mxA = fmaxf(mxA, __shfl_xor_sync(0xffffffffu, mxA, 1));
        mxA = fmaxf(mxA, __shfl_xor_sync(0xffffffffu, mxA, 2));
        mxB = fmaxf(mxB, __shfl_xor_sync(0xffffffffu, mxB, 1));
        mxB = fmaxf(mxB, __shfl_xor_sync(0xffffffffu, mxB, 2));
        const float mnA = fmaxf(mA, mxA), mnB = fmaxf(mB, mxB);
        const float aA = fast_exp8(mA - mnA), aB = fast_exp8(mB - mnB);
        mA = mnA; mB = mnB;
        float sumA = 0.0f, sumB = 0.0f;
        #pragma unroll
        for (int nt = 0; nt < 8; nt++) {
            s[nt][0] = fast_exp8(s[nt][0] - mnA);
            s[nt][1] = fast_exp8(s[nt][1] - mnA);
            s[nt][2] = fast_exp8(s[nt][2] - mnB);
            s[nt][3] = fast_exp8(s[nt][3] - mnB);
            sumA += s[nt][0] + s[nt][1];
            sumB += s[nt][2] + s[nt][3];
        }
        lA = lA * aA + sumA;
        lB = lB * aB + sumB;
        #pragma unroll
        for (int nt = 0; nt < 8; nt++) {
            o[nt][0] *= aA; o[nt][1] *= aA;
            o[nt][2] *= aB; o[nt][3] *= aB;
        }

        // O += P V  (fp16, single MMA per (kk,nt); P fragments from accumulators)
        uint32_t pf[4][4];
        #pragma unroll
        for (int kk = 0; kk < 4; kk++) {
            pf[kk][0] = cvt_h2(s[2 * kk][0],     s[2 * kk][1]);
            pf[kk][1] = cvt_h2(s[2 * kk][2],     s[2 * kk][3]);
            pf[kk][2] = cvt_h2(s[2 * kk + 1][0], s[2 * kk + 1][1]);
            pf[kk][3] = cvt_h2(s[2 * kk + 1][2], s[2 * kk + 1][3]);
        }
        #pragma unroll
        for (int nt = 0; nt < 8; nt++) {
            const int drow = ((nt << 3) + gid) * 12;
            uint4 va = Vsm[drow + tig];        // kk=0 (x,y), kk=2 (z,w)
            uint4 vb = Vsm[drow + 4 + tig];    // kk=1 (x,y), kk=3 (z,w)
            mma16816f16(o[nt], pf[0], va.x, va.y);
            mma16816f16(o[nt], pf[1], vb.x, vb.y);
            mma16816f16(o[nt], pf[2], va.z, va.w);
            mma16816f16(o[nt], pf[3], vb.z, vb.w);
        }
    }

    // finalize partials
    lA += __shfl_xor_sync(0xffffffffu, lA, 1);
    lA += __shfl_xor_sync(0xffffffffu, lA, 2);
    lB += __shfl_xor_sync(0xffffffffu, lB, 1);
    lB += __shfl_xor_sync(0xffffffffu, lB, 2);

    const int growA = bb * SEQ + rowA;
    const int growB = bb * SEQ + rowB;
    #pragma unroll
    for (int nt = 0; nt < 8; nt++) {
        const int col = (nt << 3) + (tig << 1);
        *(float2*)&g_po[ch][(size_t)growA * DH + col] = make_float2(o[nt][0], o[nt][1]);
        *(float2*)&g_po[ch][(size_t)growB * DH + col] = make_float2(o[nt][2], o[nt][3]);
    }
    if (tig == 0) {
        g_pm[ch][growA] = mA * 0.125f; g_pl[ch][growA] = lA;
        g_pm[ch][growB] = mB * 0.125f; g_pl[ch][growB] = lB;
    }
}

// ---------------------------------------------------------------------------
__global__ __launch_bounds__(256)
void merge_kernel(float* __restrict__ out)
{
    const int t = blockIdx.x * 256 + threadIdx.x;
    const int row = t >> 4;
    const int cg  = (t & 15) << 2;
    const int q   = row & (SEQ - 1);
    const int nc  = ((q >> 6) >> 3) + 1;     // 512-key chunks

    float mstar = -3.0e38f;
    #pragma unroll 4
    for (int c = 0; c < nc; c++)
        mstar = fmaxf(mstar, g_pm[c][row]);

    float L = 0.0f;
    float4 acc = make_float4(0.f, 0.f, 0.f, 0.f);
    #pragma unroll 4
    for (int c = 0; c < nc; c++) {
        const float wgt = __expf(g_pm[c][row] - mstar);
        L += wgt * g_pl[c][row];
        float4 ov = *(const float4*)&g_po[c][(size_t)row * DH + cg];
        acc.x += wgt * ov.x; acc.y += wgt * ov.y;
        acc.z += wgt * ov.z; acc.w += wgt * ov.w;
    }
    const float inv = 1.0f / L;
    *(float4*)(out + (size_t)row * DH + cg) =
        make_float4(acc.x * inv, acc.y * inv, acc.z * inv, acc.w * inv);
}

// ---------------------------------------------------------------------------
extern "C" void kernel_launch(void* const* d_in, const int* in_sizes, int n_in,
                              void* d_out, int out_size)
{
    (void)in_sizes; (void)n_in; (void)out_size;
    const float* q  = (const float*)d_in[0];
    const float* k  = (const float*)d_in[1];
    const float* v  = (const float*)d_in[2];
    const float* wq = (const float*)d_in[3];
    const float* bq = (const float*)d_in[4];
    const float* wk = (const float*)d_in[5];
    const float* bk = (const float*)d_in[6];
    const float* wv = (const float*)d_in[7];
    const float* bv = (const float*)d_in[8];
    float* out = (float*)d_out;

    wconv_kernel<<<384, 256>>>(wq, wk, wv);
    dim3 pgrid(BATCH * SEQ / 64, 3);   // (256, 3)
    proj_mma_kernel<<<pgrid, 128>>>(q, k, v, bq, bk, bv);
    kpack_kernel<<<BATCH * SEQ * 16 / 256, 256>>>();
    vpack_kernel<<<BATCH * SEQ / 64, 256>>>();
    attn_kernel<<<ATTN_BLOCKS, 128>>>();
    merge_kernel<<<BATCH * SEQ * 16 / 256, 256>>>(out);
}

// round 13
// speedup vs baseline: 1.4962x; 1.1247x over previous
#include <cuda_runtime.h>
#include <cuda_bf16.h>
#include <cuda_fp16.h>
#include <cstdint>
#include <math.h>

#define BATCH  4
#define SEQ    4096
#define DMODEL 1024
#define DH     64
#define NCHUNK 8
#define ATTN_BLOCKS 1152    // 4 batches * 288 (sum over qt of qt/8+1)

// ---------------------------------------------------------------------------
// Scratch (device globals, no allocation)
// ---------------------------------------------------------------------------
__device__ float g_qh[BATCH * SEQ * DH];
__device__ float g_kh[BATCH * SEQ * DH];
__device__ float g_vh[BATCH * SEQ * DH];
__device__ float g_po[NCHUNK][BATCH * SEQ * DH];
__device__ float g_pm[NCHUNK][BATCH * SEQ];
__device__ float g_pl[NCHUNK][BATCH * SEQ];
__device__ uint32_t g_wh[3 * 64 * 512];   // W bf16 hi, bf16x2 words [which][n][k/2]
__device__ uint32_t g_wl[3 * 64 * 512];
// Pre-packed K as fp16 dual-ks quads: row r, e=0..7: tigp=e&3, ksp=e>>2;
// quad = {w(8ksp+tigp), w(8ksp+tigp+4), w(8ksp+16+tigp), w(8ksp+16+tigp+4)}
// where w(d2) = half2(K[2d2], K[2d2+1]). ks=ksp -> (x,y), ks=ksp+2 -> (z,w).
__device__ uint4 g_kp4[BATCH * SEQ * 8];
// Pre-packed V as fp16 dual-kk quads, transposed per 64-key tile (unchanged).
__device__ uint4 g_vp4[BATCH * SEQ * 8];

// ---------------------------------------------------------------------------
__device__ __forceinline__ void mma16816(float c[4], const uint32_t a[4],
                                         uint32_t b0, uint32_t b1) {
    asm volatile(
        "mma.sync.aligned.m16n8k16.row.col.f32.bf16.bf16.f32 "
        "{%0,%1,%2,%3}, {%4,%5,%6,%7}, {%8,%9}, {%0,%1,%2,%3};"
        : "+f"(c[0]), "+f"(c[1]), "+f"(c[2]), "+f"(c[3])
        : "r"(a[0]), "r"(a[1]), "r"(a[2]), "r"(a[3]), "r"(b0), "r"(b1));
}
__device__ __forceinline__ void mma16816f16(float c[4], const uint32_t a[4],
                                            uint32_t b0, uint32_t b1) {
    asm volatile(
        "mma.sync.aligned.m16n8k16.row.col.f32.f16.f16.f32 "
        "{%0,%1,%2,%3}, {%4,%5,%6,%7}, {%8,%9}, {%0,%1,%2,%3};"
        : "+f"(c[0]), "+f"(c[1]), "+f"(c[2]), "+f"(c[3])
        : "r"(a[0]), "r"(a[1]), "r"(a[2]), "r"(a[3]), "r"(b0), "r"(b1));
}
__device__ __forceinline__ uint32_t cvt_hi(float2 f) {
    __nv_bfloat162 h = __floats2bfloat162_rn(f.x, f.y);
    return *(uint32_t*)&h;
}
__device__ __forceinline__ uint32_t cvt_lo(float2 f, uint32_t hi) {
    __nv_bfloat162 h = *(__nv_bfloat162*)&hi;
    __nv_bfloat162 l = __floats2bfloat162_rn(f.x - __low2float(h),
                                             f.y - __high2float(h));
    return *(uint32_t*)&l;
}
__device__ __forceinline__ uint32_t cvt_h2(float a, float b) {
    __half2 h = __floats2half2_rn(a, b);
    return *(uint32_t*)&h;
}

// FMA-pipe exp(x*0.125) for x <= ~0
__device__ __forceinline__ float fast_exp8(float x) {
    x = fmaxf(x, -690.0f);
    const float C = 1.4426950408889634f * 0.125f;
    float ys = fmaf(x, C, 12582912.0f);
    int   n  = __float_as_int(ys) - 0x4B400000;
    float f  = fmaf(x, C, -(ys - 12582912.0f));
    float p  = 9.6181291e-3f;
    p = fmaf(p, f, 5.5504109e-2f);
    p = fmaf(p, f, 2.4022649e-1f);
    p = fmaf(p, f, 6.9314718e-1f);
    p = fmaf(p, f, 1.0f);
    return __int_as_float((n + 127) << 23) * p;
}

// ---------------------------------------------------------------------------
__global__ __launch_bounds__(256)
void wconv_kernel(const float* __restrict__ wq, const float* __restrict__ wk,
                  const float* __restrict__ wv)
{
    const int t = blockIdx.x * 256 + threadIdx.x;
    const int which = t >> 15;
    const int p = t & 32767;
    const float* w = (which == 0) ? wq : (which == 1) ? wk : wv;
    float2 f = *(const float2*)(w + 2 * p);
    uint32_t h = cvt_hi(f);
    g_wh[t] = h;
    g_wl[t] = cvt_lo(f, h);
}

// ---------------------------------------------------------------------------
// Repack K into fp16 dual-ks quads.
// ---------------------------------------------------------------------------
__global__ __launch_bounds__(256)
void kpack_kernel()
{
    const int t = blockIdx.x * 256 + threadIdx.x;   // 0 .. BATCH*SEQ*8-1
    const int row = t >> 3;
    const int e   = t & 7;
    const int tigp = e & 3;
    const int ksp  = e >> 2;
    const int d2a = 8 * ksp + tigp;
    const int d2b = 8 * ksp + 16 + tigp;
    const float* base = g_kh + (size_t)row * DH;
    g_kp4[t] = make_uint4(
        cvt_h2(base[2 * d2a],     base[2 * d2a + 1]),
        cvt_h2(base[2 * d2a + 8], base[2 * d2a + 9]),
        cvt_h2(base[2 * d2b],     base[2 * d2b + 1]),
        cvt_h2(base[2 * d2b + 8], base[2 * d2b + 9]));
}

// ---------------------------------------------------------------------------
// Repack V: per 64-key tile, transpose to [d][k2], fp16 dual-kk quads.
// ---------------------------------------------------------------------------
__global__ __launch_bounds__(256)
void vpack_kernel()
{
    __shared__ float Vt[64 * 65];   // [d][key]
    const int tile = blockIdx.x;
    const int tid = threadIdx.x;
    const float* vt = g_vh + (size_t)tile * 64 * DH;

    #pragma unroll
    for (int it = 0; it < 16; it++) {
        const int idx = it * 256 + tid;
        const int key = idx >> 6;
        const int d   = idx & 63;
        Vt[d * 65 + key] = vt[(size_t)key * DH + d];
    }
    __syncthreads();

    uint4* op = g_vp4 + (size_t)tile * 512;
    #pragma unroll
    for (int it = 0; it < 2; it++) {
        const int idx = it * 256 + tid;     // 0..511 = d*8 + e
        const int d = idx >> 3;
        const int e = idx & 7;
        const int tigp = e & 3;
        const int kkp  = e >> 2;
        const int k2a = 8 * kkp + tigp;
        const int k2b = 8 * kkp + 16 + tigp;
        const float* row = Vt + d * 65;
        op[idx] = make_uint4(
            cvt_h2(row[2 * k2a],      row[2 * k2a + 1]),
            cvt_h2(row[2 * k2a + 8],  row[2 * k2a + 9]),
            cvt_h2(row[2 * k2b],      row[2 * k2b + 1]),
            cvt_h2(row[2 * k2b + 8],  row[2 * k2b + 9]));
    }
}

// ---------------------------------------------------------------------------
// Projection: unchanged (bf16 3-split for accuracy).
// ---------------------------------------------------------------------------
__global__ __launch_bounds__(128)
void proj_mma_kernel(const float* __restrict__ qin, const float* __restrict__ kin,
                     const float* __restrict__ vin,
                     const float* __restrict__ bq, const float* __restrict__ bk,
                     const float* __restrict__ bv)
{
    __shared__ uint32_t Xh[64 * 36], Xl[64 * 36];
    __shared__ uint32_t Wh[64 * 36], Wl[64 * 36];

    const int which = blockIdx.y;
    const float* __restrict__ x    = (which == 0) ? qin : (which == 1) ? kin : vin;
    const float* __restrict__ bias = (which == 0) ? bq  : (which == 1) ? bk  : bv;
    float* __restrict__ out        = (which == 0) ? g_qh : (which == 1) ? g_kh : g_vh;
    const uint32_t* __restrict__ wh = g_wh + which * 32768;
    const uint32_t* __restrict__ wl = g_wl + which * 32768;

    const int tid  = threadIdx.x;
    const int warp = tid >> 5;
    const int lane = tid & 31;
    const int gid  = lane >> 2;
    const int tig  = lane & 3;
    const int row0 = blockIdx.x * 64;

    float acc[8][4] = {};

    for (int kb = 0; kb < 16; kb++) {
        __syncthreads();
        #pragma unroll
        for (int it = 0; it < 8; it++) {
            const int f = it * 128 + tid;
            const int r = f >> 4;
            const int c4 = (f & 15) << 2;
            float4 v = *(const float4*)(x + (size_t)(row0 + r) * DMODEL + kb * 64 + c4);
            uint32_t h0 = cvt_hi(make_float2(v.x, v.y));
            uint32_t h1 = cvt_hi(make_float2(v.z, v.w));
            uint32_t l0 = cvt_lo(make_float2(v.x, v.y), h0);
            uint32_t l1 = cvt_lo(make_float2(v.z, v.w), h1);
            *(uint2*)&Xh[r * 36 + (c4 >> 1)] = make_uint2(h0, h1);
            *(uint2*)&Xl[r * 36 + (c4 >> 1)] = make_uint2(l0, l1);
        }
        #pragma unroll
        for (int it = 0; it < 16; it++) {
            const int f = it * 128 + tid;
            const int n = f >> 5;
            const int k2 = f & 31;
            Wh[n * 36 + k2] = wh[n * 512 + kb * 32 + k2];
            Wl[n * 36 + k2] = wl[n * 512 + kb * 32 + k2];
        }
        __syncthreads();

        #pragma unroll
        for (int ks = 0; ks < 4; ks++) {
            const int d2 = (ks << 3) + tig;
            const int ra = (warp << 4) + gid;
            uint32_t ah[4], al[4];
            ah[0] = Xh[ra * 36 + d2];        al[0] = Xl[ra * 36 + d2];
            ah[1] = Xh[(ra + 8) * 36 + d2];  al[1] = Xl[(ra + 8) * 36 + d2];
            ah[2] = Xh[ra * 36 + d2 + 4];    al[2] = Xl[ra * 36 + d2 + 4];
            ah[3] = Xh[(ra + 8) * 36 + d2 + 4]; al[3] = Xl[(ra + 8) * 36 + d2 + 4];
            #pragma unroll
            for (int nt = 0; nt < 8; nt++) {
                const int nr = (nt << 3) + gid;
                const uint32_t bh0 = Wh[nr * 36 + d2], bh1 = Wh[nr * 36 + d2 + 4];
                const uint32_t bl0 = Wl[nr * 36 + d2], bl1 = Wl[nr * 36 + d2 + 4];
                mma16816(acc[nt], ah, bh0, bh1);
                mma16816(acc[nt], ah, bl0, bl1);
                mma16816(acc[nt], al, bh0, bh1);
            }
        }
    }

    const int row = row0 + (warp << 4) + gid;
    #pragma unroll
    for (int nt = 0; nt < 8; nt++) {
        const int col = (nt << 3) + (tig << 1);
        const float b0 = bias[col], b1 = bias[col + 1];
        *(float2*)(out + (size_t)row * DH + col) =
            make_float2(acc[nt][0] + b0, acc[nt][1] + b1);
        *(float2*)(out + (size_t)(row + 8) * DH + col) =
            make_float2(acc[nt][2] + b0, acc[nt][3] + b1);
    }
}

// ---------------------------------------------------------------------------
// Flash attention, split-KV. QK^T = fp16 (32 MMAs), PV = fp16 (32 MMAs).
// ---------------------------------------------------------------------------
__global__ __launch_bounds__(128, 3)
void attn_kernel()
{
    __shared__ uint4 Ksm[64 * 12];   // [key][e] fp16 dual-ks quads (8 used/row)
    __shared__ uint4 Vsm[64 * 12];   // [d][e]  fp16 dual-kk quads (8 used/row)

    const int tid  = threadIdx.x;
    const int warp = tid >> 5;
    const int lane = tid & 31;
    const int gid  = lane >> 2;
    const int tig  = lane & 3;

    const int bgid = (ATTN_BLOCKS - 1) - blockIdx.x;
    const int bb   = bgid / 288;
    const int r    = bgid - bb * 288;
    int a = 0;
    #pragma unroll
    for (int t = 1; t < 8; t++)
        if (4 * t * (t + 1) <= r) a = t;       // octave: qt in [8a, 8a+8)
    const int rr = r - 4 * a * (a + 1);
    const int qt = 8 * a + rr / (a + 1);
    const int ch = rr - (rr / (a + 1)) * (a + 1);

    const int q0  = qt * 64;
    const int kt0 = ch * 8;
    const int kt1 = min(kt0 + 7, qt);

    const float* __restrict__ qh = g_qh + (size_t)bb * SEQ * DH;
    const uint4* __restrict__ kp4 = g_kp4 + (size_t)bb * SEQ * 8;

    // Q fragments as fp16, once
    uint32_t qf[4][4];
    const int rowA = q0 + (warp << 4) + gid;
    const int rowB = rowA + 8;
    {
        #pragma unroll
        for (int ks = 0; ks < 4; ks++) {
            const float* pA = qh + (size_t)rowA * DH + (ks << 4) + (tig << 1);
            const float* pB = qh + (size_t)rowB * DH + (ks << 4) + (tig << 1);
            float2 f0 = *(const float2*)(pA);
            float2 f1 = *(const float2*)(pB);
            float2 f2 = *(const float2*)(pA + 8);
            float2 f3 = *(const float2*)(pB + 8);
            qf[ks][0] = cvt_h2(f0.x, f0.y);
            qf[ks][1] = cvt_h2(f1.x, f1.y);
            qf[ks][2] = cvt_h2(f2.x, f2.y);
            qf[ks][3] = cvt_h2(f3.x, f3.y);
        }
    }

    float o[8][4] = {};
    float mA = -3.0e38f, mB = -3.0e38f, lA = 0.0f, lB = 0.0f;

    for (int kt = kt0; kt <= kt1; kt++) {
        const int k0 = kt * 64;
        const uint4* vp4 = g_vp4 + ((size_t)bb * 64 + kt) * 512;
        __syncthreads();
        // stage K + V: 4 uint4/thread each
        #pragma unroll
        for (int it = 0; it < 4; it++) {
            const int f = it * 128 + tid;
            const int rk = f >> 3;
            const int c  = f & 7;
            Ksm[rk * 12 + c] = kp4[(size_t)(k0 + rk) * 8 + c];
            Vsm[rk * 12 + c] = vp4[rk * 8 + c];
        }
        __syncthreads();

        // S = Q K^T (fp16, 1 MMA per (ks,nt) pair-packed: 32 total)
        float s[8][4] = {};
        #pragma unroll
        for (int nt = 0; nt < 8; nt++) {
            const int krow = ((nt << 3) + gid) * 12;
            uint4 ka = Ksm[krow + tig];        // ks=0 (x,y), ks=2 (z,w)
            uint4 kb = Ksm[krow + 4 + tig];    // ks=1 (x,y), ks=3 (z,w)
            mma16816f16(s[nt], qf[0], ka.x, ka.y);
            mma16816f16(s[nt], qf[1], kb.x, kb.y);
            mma16816f16(s[nt], qf[2], ka.z, ka.w);
            mma16816f16(s[nt], qf[3], kb.z, kb.w);
        }

        // causal mask on raw scores (diagonal tile only)
        if (kt == qt) {
            #pragma unroll
            for (int nt = 0; nt < 8; nt++) {
                const int cb = k0 + (nt << 3) + (tig << 1);
                if (cb     > rowA) s[nt][0] = -1.0e30f;
                if (cb + 1 > rowA) s[nt][1] = -1.0e30f;
                if (cb     > rowB) s[nt][2] = -1.0e30f;
                if (cb + 1 > rowB) s[nt][3] = -1.0e30f;
            }
        }

        // online softmax on raw scores; exp folds in the 1/8 scale
        float mxA = -3.0e38f, mxB = -3.0e38f;
        #pragma unroll
        for (int nt = 0; nt < 8; nt++) {
            mxA = fmaxf(mxA, fmaxf(s[nt][0], s[nt][1]));
            mxB = fmaxf(mxB, fmaxf(s[nt][2], s[nt][3]));
        }
        mxA = fmaxf(mxA, __shfl_xor_sync(0xffffffffu, mxA, 1));
        mxA = fmaxf(mxA, __shfl_xor_sync(0xffffffffu, mxA, 2));
        mxB = fmaxf(mxB, __shfl_xor_sync(0xffffffffu, mxB, 1));
        mxB = fmaxf(mxB, __shfl_xor_sync(0xffffffffu, mxB, 2));
        const float mnA = fmaxf(mA, mxA), mnB = fmaxf(mB, mxB);
        const float aA = fast_exp8(mA - mnA), aB = fast_exp8(mB - mnB);
        mA = mnA; mB = mnB;
        float sumA = 0.0f, sumB = 0.0f;
        #pragma unroll
        for (int nt = 0; nt < 8; nt++) {
            s[nt][0] = fast_exp8(s[nt][0] - mnA);
            s[nt][1] = fast_exp8(s[nt][1] - mnA);
            s[nt][2] = fast_exp8(s[nt][2] - mnB);
            s[nt][3] = fast_exp8(s[nt][3] - mnB);
            sumA += s[nt][0] + s[nt][1];
            sumB += s[nt][2] + s[nt][3];
        }
        lA = lA * aA + sumA;
        lB = lB * aB + sumB;
        #pragma unroll
        for (int nt = 0; nt < 8; nt++) {
            o[nt][0] *= aA; o[nt][1] *= aA;
            o[nt][2] *= aB; o[nt][3] *= aB;
        }

        // O += P V  (fp16, single MMA per (kk,nt))
        uint32_t pf[4][4];
        #pragma unroll
        for (int kk = 0; kk < 4; kk++) {
            pf[kk][0] = cvt_h2(s[2 * kk][0],     s[2 * kk][1]);
            pf[kk][1] = cvt_h2(s[2 * kk][2],     s[2 * kk][3]);
            pf[kk][2] = cvt_h2(s[2 * kk + 1][0], s[2 * kk + 1][1]);
            pf[kk][3] = cvt_h2(s[2 * kk + 1][2], s[2 * kk + 1][3]);
        }
        #pragma unroll
        for (int nt = 0; nt < 8; nt++) {
            const int drow = ((nt << 3) + gid) * 12;
            uint4 va = Vsm[drow + tig];        // kk=0 (x,y), kk=2 (z,w)
            uint4 vb = Vsm[drow + 4 + tig];    // kk=1 (x,y), kk=3 (z,w)
            mma16816f16(o[nt], pf[0], va.x, va.y);
            mma16816f16(o[nt], pf[1], vb.x, vb.y);
            mma16816f16(o[nt], pf[2], va.z, va.w);
            mma16816f16(o[nt], pf[3], vb.z, vb.w);
        }
    }

    // finalize partials
    lA += __shfl_xor_sync(0xffffffffu, lA, 1);
    lA += __shfl_xor_sync(0xffffffffu, lA, 2);
    lB += __shfl_xor_sync(0xffffffffu, lB, 1);
    lB += __shfl_xor_sync(0xffffffffu, lB, 2);

    const int growA = bb * SEQ + rowA;
    const int growB = bb * SEQ + rowB;
    #pragma unroll
    for (int nt = 0; nt < 8; nt++) {
        const int col = (nt << 3) + (tig << 1);
        *(float2*)&g_po[ch][(size_t)growA * DH + col] = make_float2(o[nt][0], o[nt][1]);
        *(float2*)&g_po[ch][(size_t)growB * DH + col] = make_float2(o[nt][2], o[nt][3]);
    }
    if (tig == 0) {
        g_pm[ch][growA] = mA * 0.125f; g_pl[ch][growA] = lA;
        g_pm[ch][growB] = mB * 0.125f; g_pl[ch][growB] = lB;
    }
}

// ---------------------------------------------------------------------------
__global__ __launch_bounds__(256)
void merge_kernel(float* __restrict__ out)
{
    const int t = blockIdx.x * 256 + threadIdx.x;
    const int row = t >> 4;
    const int cg  = (t & 15) << 2;
    const int q   = row & (SEQ - 1);
    const int nc  = ((q >> 6) >> 3) + 1;     // 512-key chunks

    float mstar = -3.0e38f;
    #pragma unroll 4
    for (int c = 0; c < nc; c++)
        mstar = fmaxf(mstar, g_pm[c][row]);

    float L = 0.0f;
    float4 acc = make_float4(0.f, 0.f, 0.f, 0.f);
    #pragma unroll 4
    for (int c = 0; c < nc; c++) {
        const float wgt = __expf(g_pm[c][row] - mstar);
        L += wgt * g_pl[c][row];
        float4 ov = *(const float4*)&g_po[c][(size_t)row * DH + cg];
        acc.x += wgt * ov.x; acc.y += wgt * ov.y;
        acc.z += wgt * ov.z; acc.w += wgt * ov.w;
    }
    const float inv = 1.0f / L;
    *(float4*)(out + (size_t)row * DH + cg) =
        make_float4(acc.x * inv, acc.y * inv, acc.z * inv, acc.w * inv);
}

// ---------------------------------------------------------------------------
extern "C" void kernel_launch(void* const* d_in, const int* in_sizes, int n_in,
                              void* d_out, int out_size)
{
    (void)in_sizes; (void)n_in; (void)out_size;
    const float* q  = (const float*)d_in[0];
    const float* k  = (const float*)d_in[1];
    const float* v  = (const float*)d_in[2];
    const float* wq = (const float*)d_in[3];
    const float* bq = (const float*)d_in[4];
    const float* wk = (const float*)d_in[5];
    const float* bk = (const float*)d_in[6];
    const float* wv = (const float*)d_in[7];
    const float* bv = (const float*)d_in[8];
    float* out = (float*)d_out;

    wconv_kernel<<<384, 256>>>(wq, wk, wv);
    dim3 pgrid(BATCH * SEQ / 64, 3);   // (256, 3)
    proj_mma_kernel<<<pgrid, 128>>>(q, k, v, bq, bk, bv);
    kpack_kernel<<<BATCH * SEQ * 8 / 256, 256>>>();
    vpack_kernel<<<BATCH * SEQ / 64, 256>>>();
    attn_kernel<<<ATTN_BLOCKS, 128>>>();
    merge_kernel<<<BATCH * SEQ * 16 / 256, 256>>>(out);
}

// round 14
// speedup vs baseline: 1.8336x; 1.2255x over previous
#include <cuda_runtime.h>
#include <cuda_bf16.h>
#include <cuda_fp16.h>
#include <cstdint>
#include <math.h>

#define BATCH  4
#define SEQ    4096
#define DMODEL 1024
#define DH     64
#define NCHUNK 8
#define ATTN_BLOCKS 1152    // 4 batches * 288 (sum over qt of qt/8+1)

// ---------------------------------------------------------------------------
// Scratch (device globals, no allocation)
// ---------------------------------------------------------------------------
__device__ float g_qh[BATCH * SEQ * DH];
__device__ float g_kh[BATCH * SEQ * DH];
__device__ float g_vh[BATCH * SEQ * DH];
__device__ float g_po[NCHUNK][BATCH * SEQ * DH];
__device__ float g_pm[NCHUNK][BATCH * SEQ];
__device__ float g_pl[NCHUNK][BATCH * SEQ];
__device__ uint32_t g_wf[3 * 64 * 512];   // W fp16x2 words [which][n][k/2]
// Pre-packed K as fp16 dual-ks quads (layout as round 13).
__device__ uint4 g_kp4[BATCH * SEQ * 8];
// Pre-packed V as fp16 dual-kk quads, transposed per 64-key tile.
__device__ uint4 g_vp4[BATCH * SEQ * 8];

// ---------------------------------------------------------------------------
__device__ __forceinline__ void mma16816f16(float c[4], const uint32_t a[4],
                                            uint32_t b0, uint32_t b1) {
    asm volatile(
        "mma.sync.aligned.m16n8k16.row.col.f32.f16.f16.f32 "
        "{%0,%1,%2,%3}, {%4,%5,%6,%7}, {%8,%9}, {%0,%1,%2,%3};"
        : "+f"(c[0]), "+f"(c[1]), "+f"(c[2]), "+f"(c[3])
        : "r"(a[0]), "r"(a[1]), "r"(a[2]), "r"(a[3]), "r"(b0), "r"(b1));
}
__device__ __forceinline__ uint32_t cvt_h2(float a, float b) {
    __half2 h = __floats2half2_rn(a, b);
    return *(uint32_t*)&h;
}
__device__ __forceinline__ uint32_t cvt_h2lo(float2 f, uint32_t hi) {
    __half2 h = *(__half2*)&hi;
    float2 hf = __half22float2(h);
    return cvt_h2(f.x - hf.x, f.y - hf.y);
}

// exp(x/8) via MUFU: single mul + EX2 (accuracy ~2^-22)
#define LOG2E_8 0.18033688011112042f
__device__ __forceinline__ float exp8(float x) { return exp2f(x * LOG2E_8); }

// ---------------------------------------------------------------------------
__global__ __launch_bounds__(256)
void wconv_kernel(const float* __restrict__ wq, const float* __restrict__ wk,
                  const float* __restrict__ wv)
{
    const int t = blockIdx.x * 256 + threadIdx.x;
    const int which = t >> 15;
    const int p = t & 32767;
    const float* w = (which == 0) ? wq : (which == 1) ? wk : wv;
    float2 f = *(const float2*)(w + 2 * p);
    g_wf[t] = cvt_h2(f.x, f.y);
}

// ---------------------------------------------------------------------------
// Repack K into fp16 dual-ks quads (unchanged from round 13).
// ---------------------------------------------------------------------------
__global__ __launch_bounds__(256)
void kpack_kernel()
{
    const int t = blockIdx.x * 256 + threadIdx.x;   // 0 .. BATCH*SEQ*8-1
    const int row = t >> 3;
    const int e   = t & 7;
    const int tigp = e & 3;
    const int ksp  = e >> 2;
    const int d2a = 8 * ksp + tigp;
    const int d2b = 8 * ksp + 16 + tigp;
    const float* base = g_kh + (size_t)row * DH;
    g_kp4[t] = make_uint4(
        cvt_h2(base[2 * d2a],     base[2 * d2a + 1]),
        cvt_h2(base[2 * d2a + 8], base[2 * d2a + 9]),
        cvt_h2(base[2 * d2b],     base[2 * d2b + 1]),
        cvt_h2(base[2 * d2b + 8], base[2 * d2b + 9]));
}

// ---------------------------------------------------------------------------
// Repack V (unchanged from round 13).
// ---------------------------------------------------------------------------
__global__ __launch_bounds__(256)
void vpack_kernel()
{
    __shared__ float Vt[64 * 65];   // [d][key]
    const int tile = blockIdx.x;
    const int tid = threadIdx.x;
    const float* vt = g_vh + (size_t)tile * 64 * DH;

    #pragma unroll
    for (int it = 0; it < 16; it++) {
        const int idx = it * 256 + tid;
        const int key = idx >> 6;
        const int d   = idx & 63;
        Vt[d * 65 + key] = vt[(size_t)key * DH + d];
    }
    __syncthreads();

    uint4* op = g_vp4 + (size_t)tile * 512;
    #pragma unroll
    for (int it = 0; it < 2; it++) {
        const int idx = it * 256 + tid;     // 0..511 = d*8 + e
        const int d = idx >> 3;
        const int e = idx & 7;
        const int tigp = e & 3;
        const int kkp  = e >> 2;
        const int k2a = 8 * kkp + tigp;
        const int k2b = 8 * kkp + 16 + tigp;
        const float* row = Vt + d * 65;
        op[idx] = make_uint4(
            cvt_h2(row[2 * k2a],      row[2 * k2a + 1]),
            cvt_h2(row[2 * k2a + 8],  row[2 * k2a + 9]),
            cvt_h2(row[2 * k2b],      row[2 * k2b + 1]),
            cvt_h2(row[2 * k2b + 8],  row[2 * k2b + 9]));
    }
}

// ---------------------------------------------------------------------------
// Projection: fp16 X-split-only (2 MMAs per fragment pair), W single fp16.
// Block = 64 rows x 64 n, 4 warps, K chunked by 64.
// ---------------------------------------------------------------------------
__global__ __launch_bounds__(128)
void proj_mma_kernel(const float* __restrict__ qin, const float* __restrict__ kin,
                     const float* __restrict__ vin,
                     const float* __restrict__ bq, const float* __restrict__ bk,
                     const float* __restrict__ bv)
{
    __shared__ uint32_t Xh[64 * 36], Xl[64 * 36];
    __shared__ uint32_t Wf[64 * 36];

    const int which = blockIdx.y;
    const float* __restrict__ x    = (which == 0) ? qin : (which == 1) ? kin : vin;
    const float* __restrict__ bias = (which == 0) ? bq  : (which == 1) ? bk  : bv;
    float* __restrict__ out        = (which == 0) ? g_qh : (which == 1) ? g_kh : g_vh;
    const uint32_t* __restrict__ wf = g_wf + which * 32768;

    const int tid  = threadIdx.x;
    const int warp = tid >> 5;
    const int lane = tid & 31;
    const int gid  = lane >> 2;
    const int tig  = lane & 3;
    const int row0 = blockIdx.x * 64;

    float acc[8][4] = {};

    for (int kb = 0; kb < 16; kb++) {
        __syncthreads();
        #pragma unroll
        for (int it = 0; it < 8; it++) {
            const int f = it * 128 + tid;
            const int r = f >> 4;
            const int c4 = (f & 15) << 2;
            float4 v = *(const float4*)(x + (size_t)(row0 + r) * DMODEL + kb * 64 + c4);
            uint32_t h0 = cvt_h2(v.x, v.y);
            uint32_t h1 = cvt_h2(v.z, v.w);
            uint32_t l0 = cvt_h2lo(make_float2(v.x, v.y), h0);
            uint32_t l1 = cvt_h2lo(make_float2(v.z, v.w), h1);
            *(uint2*)&Xh[r * 36 + (c4 >> 1)] = make_uint2(h0, h1);
            *(uint2*)&Xl[r * 36 + (c4 >> 1)] = make_uint2(l0, l1);
        }
        #pragma unroll
        for (int it = 0; it < 16; it++) {
            const int f = it * 128 + tid;
            const int n = f >> 5;
            const int k2 = f & 31;
            Wf[n * 36 + k2] = wf[n * 512 + kb * 32 + k2];
        }
        __syncthreads();

        #pragma unroll
        for (int ks = 0; ks < 4; ks++) {
            const int d2 = (ks << 3) + tig;
            const int ra = (warp << 4) + gid;
            uint32_t ah[4], al[4];
            ah[0] = Xh[ra * 36 + d2];        al[0] = Xl[ra * 36 + d2];
            ah[1] = Xh[(ra + 8) * 36 + d2];  al[1] = Xl[(ra + 8) * 36 + d2];
            ah[2] = Xh[ra * 36 + d2 + 4];    al[2] = Xl[ra * 36 + d2 + 4];
            ah[3] = Xh[(ra + 8) * 36 + d2 + 4]; al[3] = Xl[(ra + 8) * 36 + d2 + 4];
            #pragma unroll
            for (int nt = 0; nt < 8; nt++) {
                const int nr = (nt << 3) + gid;
                const uint32_t b0 = Wf[nr * 36 + d2], b1 = Wf[nr * 36 + d2 + 4];
                mma16816f16(acc[nt], ah, b0, b1);
                mma16816f16(acc[nt], al, b0, b1);
            }
        }
    }

    const int row = row0 + (warp << 4) + gid;
    #pragma unroll
    for (int nt = 0; nt < 8; nt++) {
        const int col = (nt << 3) + (tig << 1);
        const float b0 = bias[col], b1 = bias[col + 1];
        *(float2*)(out + (size_t)row * DH + col) =
            make_float2(acc[nt][0] + b0, acc[nt][1] + b1);
        *(float2*)(out + (size_t)(row + 8) * DH + col) =
            make_float2(acc[nt][2] + b0, acc[nt][3] + b1);
    }
}

// ---------------------------------------------------------------------------
// Flash attention, split-KV. QK^T fp16 (32 MMAs), PV fp16 (32 MMAs),
// exp on MUFU (exp2f).
// ---------------------------------------------------------------------------
__global__ __launch_bounds__(128, 3)
void attn_kernel()
{
    __shared__ uint4 Ksm[64 * 12];   // [key][e] fp16 dual-ks quads (8 used/row)
    __shared__ uint4 Vsm[64 * 12];   // [d][e]  fp16 dual-kk quads (8 used/row)

    const int tid  = threadIdx.x;
    const int warp = tid >> 5;
    const int lane = tid & 31;
    const int gid  = lane >> 2;
    const int tig  = lane & 3;

    const int bgid = (ATTN_BLOCKS - 1) - blockIdx.x;
    const int bb   = bgid / 288;
    const int r    = bgid - bb * 288;
    int a = 0;
    #pragma unroll
    for (int t = 1; t < 8; t++)
        if (4 * t * (t + 1) <= r) a = t;       // octave: qt in [8a, 8a+8)
    const int rr = r - 4 * a * (a + 1);
    const int qt = 8 * a + rr / (a + 1);
    const int ch = rr - (rr / (a + 1)) * (a + 1);

    const int q0  = qt * 64;
    const int kt0 = ch * 8;
    const int kt1 = min(kt0 + 7, qt);

    const float* __restrict__ qh = g_qh + (size_t)bb * SEQ * DH;
    const uint4* __restrict__ kp4 = g_kp4 + (size_t)bb * SEQ * 8;

    // Q fragments as fp16, once
    uint32_t qf[4][4];
    const int rowA = q0 + (warp << 4) + gid;
    const int rowB = rowA + 8;
    {
        #pragma unroll
        for (int ks = 0; ks < 4; ks++) {
            const float* pA = qh + (size_t)rowA * DH + (ks << 4) + (tig << 1);
            const float* pB = qh + (size_t)rowB * DH + (ks << 4) + (tig << 1);
            float2 f0 = *(const float2*)(pA);
            float2 f1 = *(const float2*)(pB);
            float2 f2 = *(const float2*)(pA + 8);
            float2 f3 = *(const float2*)(pB + 8);
            qf[ks][0] = cvt_h2(f0.x, f0.y);
            qf[ks][1] = cvt_h2(f1.x, f1.y);
            qf[ks][2] = cvt_h2(f2.x, f2.y);
            qf[ks][3] = cvt_h2(f3.x, f3.y);
        }
    }

    float o[8][4] = {};
    float mA = -3.0e38f, mB = -3.0e38f, lA = 0.0f, lB = 0.0f;

    for (int kt = kt0; kt <= kt1; kt++) {
        const int k0 = kt * 64;
        const uint4* vp4 = g_vp4 + ((size_t)bb * 64 + kt) * 512;
        __syncthreads();
        #pragma unroll
        for (int it = 0; it < 4; it++) {
            const int f = it * 128 + tid;
            const int rk = f >> 3;
            const int c  = f & 7;
            Ksm[rk * 12 + c] = kp4[(size_t)(k0 + rk) * 8 + c];
            Vsm[rk * 12 + c] = vp4[rk * 8 + c];
        }
        __syncthreads();

        // S = Q K^T (fp16, 32 MMAs)
        float s[8][4] = {};
        #pragma unroll
        for (int nt = 0; nt < 8; nt++) {
            const int krow = ((nt << 3) + gid) * 12;
            uint4 ka = Ksm[krow + tig];        // ks=0 (x,y), ks=2 (z,w)
            uint4 kb = Ksm[krow + 4 + tig];    // ks=1 (x,y), ks=3 (z,w)
            mma16816f16(s[nt], qf[0], ka.x, ka.y);
            mma16816f16(s[nt], qf[1], kb.x, kb.y);
            mma16816f16(s[nt], qf[2], ka.z, ka.w);
            mma16816f16(s[nt], qf[3], kb.z, kb.w);
        }

        // causal mask on raw scores (diagonal tile only)
        if (kt == qt) {
            #pragma unroll
            for (int nt = 0; nt < 8; nt++) {
                const int cb = k0 + (nt << 3) + (tig << 1);
                if (cb     > rowA) s[nt][0] = -1.0e30f;
                if (cb + 1 > rowA) s[nt][1] = -1.0e30f;
                if (cb     > rowB) s[nt][2] = -1.0e30f;
                if (cb + 1 > rowB) s[nt][3] = -1.0e30f;
            }
        }

        // online softmax on raw scores; exp folds in the 1/8 scale (MUFU)
        float mxA = -3.0e38f, mxB = -3.0e38f;
        #pragma unroll
        for (int nt = 0; nt < 8; nt++) {
            mxA = fmaxf(mxA, fmaxf(s[nt][0], s[nt][1]));
            mxB = fmaxf(mxB, fmaxf(s[nt][2], s[nt][3]));
        }
        mxA = fmaxf(mxA, __shfl_xor_sync(0xffffffffu, mxA, 1));
        mxA = fmaxf(mxA, __shfl_xor_sync(0xffffffffu, mxA, 2));
        mxB = fmaxf(mxB, __shfl_xor_sync(0xffffffffu, mxB, 1));
        mxB = fmaxf(mxB, __shfl_xor_sync(0xffffffffu, mxB, 2));
        const float mnA = fmaxf(mA, mxA), mnB = fmaxf(mB, mxB);
        const float aA = exp8(mA - mnA), aB = exp8(mB - mnB);
        mA = mnA; mB = mnB;
        float sumA = 0.0f, sumB = 0.0f;
        #pragma unroll
        for (int nt = 0; nt < 8; nt++) {
            s[nt][0] = exp8(s[nt][0] - mnA);
            s[nt][1] = exp8(s[nt][1] - mnA);
            s[nt][2] = exp8(s[nt][2] - mnB);
            s[nt][3] = exp8(s[nt][3] - mnB);
            sumA += s[nt][0] + s[nt][1];
            sumB += s[nt][2] + s[nt][3];
        }
        lA = lA * aA + sumA;
        lB = lB * aB + sumB;
        #pragma unroll
        for (int nt = 0; nt < 8; nt++) {
            o[nt][0] *= aA; o[nt][1] *= aA;
            o[nt][2] *= aB; o[nt][3] *= aB;
        }

        // O += P V  (fp16, 32 MMAs)
        uint32_t pf[4][4];
        #pragma unroll
        for (int kk = 0; kk < 4; kk++) {
            pf[kk][0] = cvt_h2(s[2 * kk][0],     s[2 * kk][1]);
            pf[kk][1] = cvt_h2(s[2 * kk][2],     s[2 * kk][3]);
            pf[kk][2] = cvt_h2(s[2 * kk + 1][0], s[2 * kk + 1][1]);
            pf[kk][3] = cvt_h2(s[2 * kk + 1][2], s[2 * kk + 1][3]);
        }
        #pragma unroll
        for (int nt = 0; nt < 8; nt++) {
            const int drow = ((nt << 3) + gid) * 12;
            uint4 va = Vsm[drow + tig];        // kk=0 (x,y), kk=2 (z,w)
            uint4 vb = Vsm[drow + 4 + tig];    // kk=1 (x,y), kk=3 (z,w)
            mma16816f16(o[nt], pf[0], va.x, va.y);
            mma16816f16(o[nt], pf[1], vb.x, vb.y);
            mma16816f16(o[nt], pf[2], va.z, va.w);
            mma16816f16(o[nt], pf[3], vb.z, vb.w);
        }
    }

    // finalize partials
    lA += __shfl_xor_sync(0xffffffffu, lA, 1);
    lA += __shfl_xor_sync(0xffffffffu, lA, 2);
    lB += __shfl_xor_sync(0xffffffffu, lB, 1);
    lB += __shfl_xor_sync(0xffffffffu, lB, 2);

    const int growA = bb * SEQ + rowA;
    const int growB = bb * SEQ + rowB;
    #pragma unroll
    for (int nt = 0; nt < 8; nt++) {
        const int col = (nt << 3) + (tig << 1);
        *(float2*)&g_po[ch][(size_t)growA * DH + col] = make_float2(o[nt][0], o[nt][1]);
        *(float2*)&g_po[ch][(size_t)growB * DH + col] = make_float2(o[nt][2], o[nt][3]);
    }
    if (tig == 0) {
        g_pm[ch][growA] = mA * 0.125f; g_pl[ch][growA] = lA;
        g_pm[ch][growB] = mB * 0.125f; g_pl[ch][growB] = lB;
    }
}

// ---------------------------------------------------------------------------
__global__ __launch_bounds__(256)
void merge_kernel(float* __restrict__ out)
{
    const int t = blockIdx.x * 256 + threadIdx.x;
    const int row = t >> 4;
    const int cg  = (t & 15) << 2;
    const int q   = row & (SEQ - 1);
    const int nc  = ((q >> 6) >> 3) + 1;     // 512-key chunks

    float mstar = -3.0e38f;
    #pragma unroll 4
    for (int c = 0; c < nc; c++)
        mstar = fmaxf(mstar, g_pm[c][row]);

    float L = 0.0f;
    float4 acc = make_float4(0.f, 0.f, 0.f, 0.f);
    #pragma unroll 4
    for (int c = 0; c < nc; c++) {
        const float wgt = __expf(g_pm[c][row] - mstar);
        L += wgt * g_pl[c][row];
        float4 ov = *(const float4*)&g_po[c][(size_t)row * DH + cg];
        acc.x += wgt * ov.x; acc.y += wgt * ov.y;
        acc.z += wgt * ov.z; acc.w += wgt * ov.w;
    }
    const float inv = 1.0f / L;
    *(float4*)(out + (size_t)row * DH + cg) =
        make_float4(acc.x * inv, acc.y * inv, acc.z * inv, acc.w * inv);
}

// ---------------------------------------------------------------------------
extern "C" void kernel_launch(void* const* d_in, const int* in_sizes, int n_in,
                              void* d_out, int out_size)
{
    (void)in_sizes; (void)n_in; (void)out_size;
    const float* q  = (const float*)d_in[0];
    const float* k  = (const float*)d_in[1];
    const float* v  = (const float*)d_in[2];
    const float* wq = (const float*)d_in[3];
    const float* bq = (const float*)d_in[4];
    const float* wk = (const float*)d_in[5];
    const float* bk = (const float*)d_in[6];
    const float* wv = (const float*)d_in[7];
    const float* bv = (const float*)d_in[8];
    float* out = (float*)d_out;

    wconv_kernel<<<384, 256>>>(wq, wk, wv);
    dim3 pgrid(BATCH * SEQ / 64, 3);   // (256, 3)
    proj_mma_kernel<<<pgrid, 128>>>(q, k, v, bq, bk, bv);
    kpack_kernel<<<BATCH * SEQ * 8 / 256, 256>>>();
    vpack_kernel<<<BATCH * SEQ / 64, 256>>>();
    attn_kernel<<<ATTN_BLOCKS, 128>>>();
    merge_kernel<<<BATCH * SEQ * 16 / 256, 256>>>(out);
}

// round 15
// speedup vs baseline: 1.9401x; 1.0581x over previous
#include <cuda_runtime.h>
#include <cuda_bf16.h>
#include <cuda_fp16.h>
#include <cstdint>
#include <math.h>

#define BATCH  4
#define SEQ    4096
#define DMODEL 1024
#define DH     64
#define NCHUNK 8
#define ATTN_BLOCKS 1152    // 4 batches * 288 (sum over qt of qt/8+1)

// ---------------------------------------------------------------------------
// Scratch (device globals, no allocation)
// ---------------------------------------------------------------------------
__device__ float g_qh[BATCH * SEQ * DH];
__device__ float g_kh[BATCH * SEQ * DH];
__device__ float g_vh[BATCH * SEQ * DH];
__device__ float g_po[NCHUNK][BATCH * SEQ * DH];
__device__ float g_pm[NCHUNK][BATCH * SEQ];
__device__ float g_pl[NCHUNK][BATCH * SEQ];
__device__ uint32_t g_wf[3 * 64 * 512];   // W fp16x2 words [which][n][k/2]
// Pre-packed K as fp16 dual-ks quads.
__device__ uint4 g_kp4[BATCH * SEQ * 8];
// Pre-packed V as fp16 dual-kk quads, transposed per 64-key tile.
__device__ uint4 g_vp4[BATCH * SEQ * 8];

// ---------------------------------------------------------------------------
__device__ __forceinline__ void mma16816f16(float c[4], const uint32_t a[4],
                                            uint32_t b0, uint32_t b1) {
    asm volatile(
        "mma.sync.aligned.m16n8k16.row.col.f32.f16.f16.f32 "
        "{%0,%1,%2,%3}, {%4,%5,%6,%7}, {%8,%9}, {%0,%1,%2,%3};"
        : "+f"(c[0]), "+f"(c[1]), "+f"(c[2]), "+f"(c[3])
        : "r"(a[0]), "r"(a[1]), "r"(a[2]), "r"(a[3]), "r"(b0), "r"(b1));
}
__device__ __forceinline__ uint32_t cvt_h2(float a, float b) {
    __half2 h = __floats2half2_rn(a, b);
    return *(uint32_t*)&h;
}
__device__ __forceinline__ uint32_t cvt_h2lo(float2 f, uint32_t hi) {
    __half2 h = *(__half2*)&hi;
    float2 hf = __half22float2(h);
    return cvt_h2(f.x - hf.x, f.y - hf.y);
}

// exp(x/8) via MUFU: single mul + EX2
#define LOG2E_8 0.18033688011112042f
__device__ __forceinline__ float exp8(float x) { return exp2f(x * LOG2E_8); }

// cp.async 16B helpers
__device__ __forceinline__ void cpa16(void* smem, const void* g) {
    uint32_t sa = (uint32_t)__cvta_generic_to_shared(smem);
    asm volatile("cp.async.cg.shared.global [%0], [%1], 16;" :: "r"(sa), "l"(g));
}
#define CPA_COMMIT() asm volatile("cp.async.commit_group;" ::: "memory")
#define CPA_WAIT0()  asm volatile("cp.async.wait_group 0;" ::: "memory")

// ---------------------------------------------------------------------------
__global__ __launch_bounds__(256)
void wconv_kernel(const float* __restrict__ wq, const float* __restrict__ wk,
                  const float* __restrict__ wv)
{
    const int t = blockIdx.x * 256 + threadIdx.x;
    const int which = t >> 15;
    const int p = t & 32767;
    const float* w = (which == 0) ? wq : (which == 1) ? wk : wv;
    float2 f = *(const float2*)(w + 2 * p);
    g_wf[t] = cvt_h2(f.x, f.y);
}

// ---------------------------------------------------------------------------
// Repack K into fp16 dual-ks quads.
// ---------------------------------------------------------------------------
__global__ __launch_bounds__(256)
void kpack_kernel()
{
    const int t = blockIdx.x * 256 + threadIdx.x;   // 0 .. BATCH*SEQ*8-1
    const int row = t >> 3;
    const int e   = t & 7;
    const int tigp = e & 3;
    const int ksp  = e >> 2;
    const int d2a = 8 * ksp + tigp;
    const int d2b = 8 * ksp + 16 + tigp;
    const float* base = g_kh + (size_t)row * DH;
    g_kp4[t] = make_uint4(
        cvt_h2(base[2 * d2a],     base[2 * d2a + 1]),
        cvt_h2(base[2 * d2a + 8], base[2 * d2a + 9]),
        cvt_h2(base[2 * d2b],     base[2 * d2b + 1]),
        cvt_h2(base[2 * d2b + 8], base[2 * d2b + 9]));
}

// ---------------------------------------------------------------------------
// Repack V: per 64-key tile, transpose to [d][k2], fp16 dual-kk quads.
// ---------------------------------------------------------------------------
__global__ __launch_bounds__(256)
void vpack_kernel()
{
    __shared__ float Vt[64 * 65];   // [d][key]
    const int tile = blockIdx.x;
    const int tid = threadIdx.x;
    const float* vt = g_vh + (size_t)tile * 64 * DH;

    #pragma unroll
    for (int it = 0; it < 16; it++) {
        const int idx = it * 256 + tid;
        const int key = idx >> 6;
        const int d   = idx & 63;
        Vt[d * 65 + key] = vt[(size_t)key * DH + d];
    }
    __syncthreads();

    uint4* op = g_vp4 + (size_t)tile * 512;
    #pragma unroll
    for (int it = 0; it < 2; it++) {
        const int idx = it * 256 + tid;     // 0..511 = d*8 + e
        const int d = idx >> 3;
        const int e = idx & 7;
        const int tigp = e & 3;
        const int kkp  = e >> 2;
        const int k2a = 8 * kkp + tigp;
        const int k2b = 8 * kkp + 16 + tigp;
        const float* row = Vt + d * 65;
        op[idx] = make_uint4(
            cvt_h2(row[2 * k2a],      row[2 * k2a + 1]),
            cvt_h2(row[2 * k2a + 8],  row[2 * k2a + 9]),
            cvt_h2(row[2 * k2b],      row[2 * k2b + 1]),
            cvt_h2(row[2 * k2b + 8],  row[2 * k2b + 9]));
    }
}

// ---------------------------------------------------------------------------
// Projection: fp16 X-split-only (2 MMAs per fragment pair) — unchanged.
// ---------------------------------------------------------------------------
__global__ __launch_bounds__(128)
void proj_mma_kernel(const float* __restrict__ qin, const float* __restrict__ kin,
                     const float* __restrict__ vin,
                     const float* __restrict__ bq, const float* __restrict__ bk,
                     const float* __restrict__ bv)
{
    __shared__ uint32_t Xh[64 * 36], Xl[64 * 36];
    __shared__ uint32_t Wf[64 * 36];

    const int which = blockIdx.y;
    const float* __restrict__ x    = (which == 0) ? qin : (which == 1) ? kin : vin;
    const float* __restrict__ bias = (which == 0) ? bq  : (which == 1) ? bk  : bv;
    float* __restrict__ out        = (which == 0) ? g_qh : (which == 1) ? g_kh : g_vh;
    const uint32_t* __restrict__ wf = g_wf + which * 32768;

    const int tid  = threadIdx.x;
    const int warp = tid >> 5;
    const int lane = tid & 31;
    const int gid  = lane >> 2;
    const int tig  = lane & 3;
    const int row0 = blockIdx.x * 64;

    float acc[8][4] = {};

    for (int kb = 0; kb < 16; kb++) {
        __syncthreads();
        #pragma unroll
        for (int it = 0; it < 8; it++) {
            const int f = it * 128 + tid;
            const int r = f >> 4;
            const int c4 = (f & 15) << 2;
            float4 v = *(const float4*)(x + (size_t)(row0 + r) * DMODEL + kb * 64 + c4);
            uint32_t h0 = cvt_h2(v.x, v.y);
            uint32_t h1 = cvt_h2(v.z, v.w);
            uint32_t l0 = cvt_h2lo(make_float2(v.x, v.y), h0);
            uint32_t l1 = cvt_h2lo(make_float2(v.z, v.w), h1);
            *(uint2*)&Xh[r * 36 + (c4 >> 1)] = make_uint2(h0, h1);
            *(uint2*)&Xl[r * 36 + (c4 >> 1)] = make_uint2(l0, l1);
        }
        #pragma unroll
        for (int it = 0; it < 16; it++) {
            const int f = it * 128 + tid;
            const int n = f >> 5;
            const int k2 = f & 31;
            Wf[n * 36 + k2] = wf[n * 512 + kb * 32 + k2];
        }
        __syncthreads();

        #pragma unroll
        for (int ks = 0; ks < 4; ks++) {
            const int d2 = (ks << 3) + tig;
            const int ra = (warp << 4) + gid;
            uint32_t ah[4], al[4];
            ah[0] = Xh[ra * 36 + d2];        al[0] = Xl[ra * 36 + d2];
            ah[1] = Xh[(ra + 8) * 36 + d2];  al[1] = Xl[(ra + 8) * 36 + d2];
            ah[2] = Xh[ra * 36 + d2 + 4];    al[2] = Xl[ra * 36 + d2 + 4];
            ah[3] = Xh[(ra + 8) * 36 + d2 + 4]; al[3] = Xl[(ra + 8) * 36 + d2 + 4];
            #pragma unroll
            for (int nt = 0; nt < 8; nt++) {
                const int nr = (nt << 3) + gid;
                const uint32_t b0 = Wf[nr * 36 + d2], b1 = Wf[nr * 36 + d2 + 4];
                mma16816f16(acc[nt], ah, b0, b1);
                mma16816f16(acc[nt], al, b0, b1);
            }
        }
    }

    const int row = row0 + (warp << 4) + gid;
    #pragma unroll
    for (int nt = 0; nt < 8; nt++) {
        const int col = (nt << 3) + (tig << 1);
        const float b0 = bias[col], b1 = bias[col + 1];
        *(float2*)(out + (size_t)row * DH + col) =
            make_float2(acc[nt][0] + b0, acc[nt][1] + b1);
        *(float2*)(out + (size_t)(row + 8) * DH + col) =
            make_float2(acc[nt][2] + b0, acc[nt][3] + b1);
    }
}

// ---------------------------------------------------------------------------
// Flash attention, split-KV, fp16 MMAs, cp.async double-buffered K/V staging.
// One __syncthreads per tile-step; loads for t+1 overlap compute of t.
// ---------------------------------------------------------------------------
__global__ __launch_bounds__(128, 3)
void attn_kernel()
{
    __shared__ uint4 Ksm[2][64 * 12];   // [buf][key][e] (8 used of 12/row)
    __shared__ uint4 Vsm[2][64 * 12];   // [buf][d][e]

    const int tid  = threadIdx.x;
    const int warp = tid >> 5;
    const int lane = tid & 31;
    const int gid  = lane >> 2;
    const int tig  = lane & 3;

    const int bgid = (ATTN_BLOCKS - 1) - blockIdx.x;
    const int bb   = bgid / 288;
    const int r    = bgid - bb * 288;
    int a = 0;
    #pragma unroll
    for (int t = 1; t < 8; t++)
        if (4 * t * (t + 1) <= r) a = t;       // octave: qt in [8a, 8a+8)
    const int rr = r - 4 * a * (a + 1);
    const int qt = 8 * a + rr / (a + 1);
    const int ch = rr - (rr / (a + 1)) * (a + 1);

    const int q0  = qt * 64;
    const int kt0 = ch * 8;
    const int kt1 = min(kt0 + 7, qt);

    const float* __restrict__ qh = g_qh + (size_t)bb * SEQ * DH;
    const uint4* __restrict__ kp4 = g_kp4 + (size_t)bb * SEQ * 8;
    const uint4* __restrict__ vpb = g_vp4 + (size_t)bb * 64 * 512;

    // indices for this thread's staging slice (4 rows x 8-entry halves)
    const int srk = tid >> 3;          // 0..15 -> rows via +16 steps
    const int sc  = tid & 7;           // 0..7

    // prefetch first tile into buf 0
    {
        const int k0 = kt0 * 64;
        const uint4* vp4 = vpb + (size_t)kt0 * 512;
        #pragma unroll
        for (int it = 0; it < 4; it++) {
            const int rk = srk + it * 16;
            cpa16(&Ksm[0][rk * 12 + sc], &kp4[(size_t)(k0 + rk) * 8 + sc]);
            cpa16(&Vsm[0][rk * 12 + sc], &vp4[rk * 8 + sc]);
        }
        CPA_COMMIT();
    }

    // Q fragments as fp16, once (overlaps with the first prefetch)
    uint32_t qf[4][4];
    const int rowA = q0 + (warp << 4) + gid;
    const int rowB = rowA + 8;
    {
        #pragma unroll
        for (int ks = 0; ks < 4; ks++) {
            const float* pA = qh + (size_t)rowA * DH + (ks << 4) + (tig << 1);
            const float* pB = qh + (size_t)rowB * DH + (ks << 4) + (tig << 1);
            float2 f0 = *(const float2*)(pA);
            float2 f1 = *(const float2*)(pB);
            float2 f2 = *(const float2*)(pA + 8);
            float2 f3 = *(const float2*)(pB + 8);
            qf[ks][0] = cvt_h2(f0.x, f0.y);
            qf[ks][1] = cvt_h2(f1.x, f1.y);
            qf[ks][2] = cvt_h2(f2.x, f2.y);
            qf[ks][3] = cvt_h2(f3.x, f3.y);
        }
    }

    float o[8][4] = {};
    float mA = -3.0e38f, mB = -3.0e38f, lA = 0.0f, lB = 0.0f;

    for (int kt = kt0; kt <= kt1; kt++) {
        const int b = (kt - kt0) & 1;
        CPA_WAIT0();
        __syncthreads();   // buf b ready for all; buf b^1 free (last read in kt-2)

        // prefetch next tile into buf b^1 (overlaps compute below)
        if (kt < kt1) {
            const int k0n = (kt + 1) * 64;
            const uint4* vp4 = vpb + (size_t)(kt + 1) * 512;
            #pragma unroll
            for (int it = 0; it < 4; it++) {
                const int rk = srk + it * 16;
                cpa16(&Ksm[b ^ 1][rk * 12 + sc], &kp4[(size_t)(k0n + rk) * 8 + sc]);
                cpa16(&Vsm[b ^ 1][rk * 12 + sc], &vp4[rk * 8 + sc]);
            }
            CPA_COMMIT();
        }

        const int k0 = kt * 64;
        // S = Q K^T (fp16, 32 MMAs)
        float s[8][4] = {};
        #pragma unroll
        for (int nt = 0; nt < 8; nt++) {
            const int krow = ((nt << 3) + gid) * 12;
            uint4 ka = Ksm[b][krow + tig];        // ks=0 (x,y), ks=2 (z,w)
            uint4 kb = Ksm[b][krow + 4 + tig];    // ks=1 (x,y), ks=3 (z,w)
            mma16816f16(s[nt], qf[0], ka.x, ka.y);
            mma16816f16(s[nt], qf[1], kb.x, kb.y);
            mma16816f16(s[nt], qf[2], ka.z, ka.w);
            mma16816f16(s[nt], qf[3], kb.z, kb.w);
        }

        // causal mask on raw scores (diagonal tile only)
        if (kt == qt) {
            #pragma unroll
            for (int nt = 0; nt < 8; nt++) {
                const int cb = k0 + (nt << 3) + (tig << 1);
                if (cb     > rowA) s[nt][0] = -1.0e30f;
                if (cb + 1 > rowA) s[nt][1] = -1.0e30f;
                if (cb     > rowB) s[nt][2] = -1.0e30f;
                if (cb + 1 > rowB) s[nt][3] = -1.0e30f;
            }
        }

        // online softmax on raw scores; exp folds in the 1/8 scale (MUFU)
        float mxA = -3.0e38f, mxB = -3.0e38f;
        #pragma unroll
        for (int nt = 0; nt < 8; nt++) {
            mxA = fmaxf(mxA, fmaxf(s[nt][0], s[nt][1]));
            mxB = fmaxf(mxB, fmaxf(s[nt][2], s[nt][3]));
        }
        mxA = fmaxf(mxA, __shfl_xor_sync(0xffffffffu, mxA, 1));
        mxA = fmaxf(mxA, __shfl_xor_sync(0xffffffffu, mxA, 2));
        mxB = fmaxf(mxB, __shfl_xor_sync(0xffffffffu, mxB, 1));
        mxB = fmaxf(mxB, __shfl_xor_sync(0xffffffffu, mxB, 2));
        const float mnA = fmaxf(mA, mxA), mnB = fmaxf(mB, mxB);
        const float aA = exp8(mA - mnA), aB = exp8(mB - mnB);
        mA = mnA; mB = mnB;
        float sumA = 0.0f, sumB = 0.0f;
        #pragma unroll
        for (int nt = 0; nt < 8; nt++) {
            s[nt][0] = exp8(s[nt][0] - mnA);
            s[nt][1] = exp8(s[nt][1] - mnA);
            s[nt][2] = exp8(s[nt][2] - mnB);
            s[nt][3] = exp8(s[nt][3] - mnB);
            sumA += s[nt][0] + s[nt][1];
            sumB += s[nt][2] + s[nt][3];
        }
        lA = lA * aA + sumA;
        lB = lB * aB + sumB;
        #pragma unroll
        for (int nt = 0; nt < 8; nt++) {
            o[nt][0] *= aA; o[nt][1] *= aA;
            o[nt][2] *= aB; o[nt][3] *= aB;
        }

        // O += P V  (fp16, 32 MMAs)
        uint32_t pf[4][4];
        #pragma unroll
        for (int kk = 0; kk < 4; kk++) {
            pf[kk][0] = cvt_h2(s[2 * kk][0],     s[2 * kk][1]);
            pf[kk][1] = cvt_h2(s[2 * kk][2],     s[2 * kk][3]);
            pf[kk][2] = cvt_h2(s[2 * kk + 1][0], s[2 * kk + 1][1]);
            pf[kk][3] = cvt_h2(s[2 * kk + 1][2], s[2 * kk + 1][3]);
        }
        #pragma unroll
        for (int nt = 0; nt < 8; nt++) {
            const int drow = ((nt << 3) + gid) * 12;
            uint4 va = Vsm[b][drow + tig];        // kk=0 (x,y), kk=2 (z,w)
            uint4 vb = Vsm[b][drow + 4 + tig];    // kk=1 (x,y), kk=3 (z,w)
            mma16816f16(o[nt], pf[0], va.x, va.y);
            mma16816f16(o[nt], pf[1], vb.x, vb.y);
            mma16816f16(o[nt], pf[2], va.z, va.w);
            mma16816f16(o[nt], pf[3], vb.z, vb.w);
        }
    }

    // finalize partials
    lA += __shfl_xor_sync(0xffffffffu, lA, 1);
    lA += __shfl_xor_sync(0xffffffffu, lA, 2);
    lB += __shfl_xor_sync(0xffffffffu, lB, 1);
    lB += __shfl_xor_sync(0xffffffffu, lB, 2);

    const int growA = bb * SEQ + rowA;
    const int growB = bb * SEQ + rowB;
    #pragma unroll
    for (int nt = 0; nt < 8; nt++) {
        const int col = (nt << 3) + (tig << 1);
        *(float2*)&g_po[ch][(size_t)growA * DH + col] = make_float2(o[nt][0], o[nt][1]);
        *(float2*)&g_po[ch][(size_t)growB * DH + col] = make_float2(o[nt][2], o[nt][3]);
    }
    if (tig == 0) {
        g_pm[ch][growA] = mA * 0.125f; g_pl[ch][growA] = lA;
        g_pm[ch][growB] = mB * 0.125f; g_pl[ch][growB] = lB;
    }
}

// ---------------------------------------------------------------------------
__global__ __launch_bounds__(256)
void merge_kernel(float* __restrict__ out)
{
    const int t = blockIdx.x * 256 + threadIdx.x;
    const int row = t >> 4;
    const int cg  = (t & 15) << 2;
    const int q   = row & (SEQ - 1);
    const int nc  = ((q >> 6) >> 3) + 1;     // 512-key chunks

    float mstar = -3.0e38f;
    #pragma unroll 4
    for (int c = 0; c < nc; c++)
        mstar = fmaxf(mstar, g_pm[c][row]);

    float L = 0.0f;
    float4 acc = make_float4(0.f, 0.f, 0.f, 0.f);
    #pragma unroll 4
    for (int c = 0; c < nc; c++) {
        const float wgt = __expf(g_pm[c][row] - mstar);
        L += wgt * g_pl[c][row];
        float4 ov = *(const float4*)&g_po[c][(size_t)row * DH + cg];
        acc.x += wgt * ov.x; acc.y += wgt * ov.y;
        acc.z += wgt * ov.z; acc.w += wgt * ov.w;
    }
    const float inv = 1.0f / L;
    *(float4*)(out + (size_t)row * DH + cg) =
        make_float4(acc.x * inv, acc.y * inv, acc.z * inv, acc.w * inv);
}

// ---------------------------------------------------------------------------
extern "C" void kernel_launch(void* const* d_in, const int* in_sizes, int n_in,
                              void* d_out, int out_size)
{
    (void)in_sizes; (void)n_in; (void)out_size;
    const float* q  = (const float*)d_in[0];
    const float* k  = (const float*)d_in[1];
    const float* v  = (const float*)d_in[2];
    const float* wq = (const float*)d_in[3];
    const float* bq = (const float*)d_in[4];
    const float* wk = (const float*)d_in[5];
    const float* bk = (const float*)d_in[6];
    const float* wv = (const float*)d_in[7];
    const float* bv = (const float*)d_in[8];
    float* out = (float*)d_out;

    wconv_kernel<<<384, 256>>>(wq, wk, wv);
    dim3 pgrid(BATCH * SEQ / 64, 3);   // (256, 3)
    proj_mma_kernel<<<pgrid, 128>>>(q, k, v, bq, bk, bv);
    kpack_kernel<<<BATCH * SEQ * 8 / 256, 256>>>();
    vpack_kernel<<<BATCH * SEQ / 64, 256>>>();
    attn_kernel<<<ATTN_BLOCKS, 128>>>();
    merge_kernel<<<BATCH * SEQ * 16 / 256, 256>>>(out);
}

// round 16
// speedup vs baseline: 1.9581x; 1.0093x over previous
#include <cuda_runtime.h>
#include <cuda_bf16.h>
#include <cuda_fp16.h>
#include <cstdint>
#include <math.h>

#define BATCH  4
#define SEQ    4096
#define DMODEL 1024
#define DH     64
#define NCHUNK 8
#define ATTN_BLOCKS 1152    // 4 batches * 288 (sum over qt of qt/8+1)

// ---------------------------------------------------------------------------
// Scratch (device globals, no allocation)
// ---------------------------------------------------------------------------
__device__ float g_qh[BATCH * SEQ * DH];
__device__ float g_kh[BATCH * SEQ * DH];
__device__ float g_vh[BATCH * SEQ * DH];
__device__ float g_po[NCHUNK][BATCH * SEQ * DH];
__device__ float g_pm[NCHUNK][BATCH * SEQ];
__device__ float g_pl[NCHUNK][BATCH * SEQ];
__device__ uint32_t g_wf[3 * 64 * 512];   // W fp16x2 words [which][n][k/2]
// Pre-packed K as fp16 dual-ks quads.
__device__ uint4 g_kp4[BATCH * SEQ * 8];
// Pre-packed V as fp16 dual-kk quads, transposed per 64-key tile.
__device__ uint4 g_vp4[BATCH * SEQ * 8];

// ---------------------------------------------------------------------------
__device__ __forceinline__ void mma16816f16(float c[4], const uint32_t a[4],
                                            uint32_t b0, uint32_t b1) {
    asm volatile(
        "mma.sync.aligned.m16n8k16.row.col.f32.f16.f16.f32 "
        "{%0,%1,%2,%3}, {%4,%5,%6,%7}, {%8,%9}, {%0,%1,%2,%3};"
        : "+f"(c[0]), "+f"(c[1]), "+f"(c[2]), "+f"(c[3])
        : "r"(a[0]), "r"(a[1]), "r"(a[2]), "r"(a[3]), "r"(b0), "r"(b1));
}
__device__ __forceinline__ uint32_t cvt_h2(float a, float b) {
    __half2 h = __floats2half2_rn(a, b);
    return *(uint32_t*)&h;
}
__device__ __forceinline__ uint32_t cvt_h2lo(float2 f, uint32_t hi) {
    __half2 h = *(__half2*)&hi;
    float2 hf = __half22float2(h);
    return cvt_h2(f.x - hf.x, f.y - hf.y);
}

// exp(x/8) via MUFU: single mul + EX2
#define LOG2E_8 0.18033688011112042f
__device__ __forceinline__ float exp8(float x) { return exp2f(x * LOG2E_8); }

// cp.async 16B helpers
__device__ __forceinline__ void cpa16(void* smem, const void* g) {
    uint32_t sa = (uint32_t)__cvta_generic_to_shared(smem);
    asm volatile("cp.async.cg.shared.global [%0], [%1], 16;" :: "r"(sa), "l"(g));
}
#define CPA_COMMIT() asm volatile("cp.async.commit_group;" ::: "memory")
#define CPA_WAIT0()  asm volatile("cp.async.wait_group 0;" ::: "memory")

// ---------------------------------------------------------------------------
__global__ __launch_bounds__(256)
void wconv_kernel(const float* __restrict__ wq, const float* __restrict__ wk,
                  const float* __restrict__ wv)
{
    const int t = blockIdx.x * 256 + threadIdx.x;
    const int which = t >> 15;
    const int p = t & 32767;
    const float* w = (which == 0) ? wq : (which == 1) ? wk : wv;
    float2 f = *(const float2*)(w + 2 * p);
    g_wf[t] = cvt_h2(f.x, f.y);
}

// ---------------------------------------------------------------------------
// Repack K into fp16 dual-ks quads.
// ---------------------------------------------------------------------------
__global__ __launch_bounds__(256)
void kpack_kernel()
{
    const int t = blockIdx.x * 256 + threadIdx.x;   // 0 .. BATCH*SEQ*8-1
    const int row = t >> 3;
    const int e   = t & 7;
    const int tigp = e & 3;
    const int ksp  = e >> 2;
    const int d2a = 8 * ksp + tigp;
    const int d2b = 8 * ksp + 16 + tigp;
    const float* base = g_kh + (size_t)row * DH;
    g_kp4[t] = make_uint4(
        cvt_h2(base[2 * d2a],     base[2 * d2a + 1]),
        cvt_h2(base[2 * d2a + 8], base[2 * d2a + 9]),
        cvt_h2(base[2 * d2b],     base[2 * d2b + 1]),
        cvt_h2(base[2 * d2b + 8], base[2 * d2b + 9]));
}

// ---------------------------------------------------------------------------
// Repack V: per 64-key tile, transpose to [d][k2], fp16 dual-kk quads.
// ---------------------------------------------------------------------------
__global__ __launch_bounds__(256)
void vpack_kernel()
{
    __shared__ float Vt[64 * 65];   // [d][key]
    const int tile = blockIdx.x;
    const int tid = threadIdx.x;
    const float* vt = g_vh + (size_t)tile * 64 * DH;

    #pragma unroll
    for (int it = 0; it < 16; it++) {
        const int idx = it * 256 + tid;
        const int key = idx >> 6;
        const int d   = idx & 63;
        Vt[d * 65 + key] = vt[(size_t)key * DH + d];
    }
    __syncthreads();

    uint4* op = g_vp4 + (size_t)tile * 512;
    #pragma unroll
    for (int it = 0; it < 2; it++) {
        const int idx = it * 256 + tid;     // 0..511 = d*8 + e
        const int d = idx >> 3;
        const int e = idx & 7;
        const int tigp = e & 3;
        const int kkp  = e >> 2;
        const int k2a = 8 * kkp + tigp;
        const int k2b = 8 * kkp + 16 + tigp;
        const float* row = Vt + d * 65;
        op[idx] = make_uint4(
            cvt_h2(row[2 * k2a],      row[2 * k2a + 1]),
            cvt_h2(row[2 * k2a + 8],  row[2 * k2a + 9]),
            cvt_h2(row[2 * k2b],      row[2 * k2b + 1]),
            cvt_h2(row[2 * k2b + 8],  row[2 * k2b + 9]));
    }
}

// ---------------------------------------------------------------------------
// Projection: fp16 X-split-only (2 MMAs per fragment pair) — unchanged.
// ---------------------------------------------------------------------------
__global__ __launch_bounds__(128)
void proj_mma_kernel(const float* __restrict__ qin, const float* __restrict__ kin,
                     const float* __restrict__ vin,
                     const float* __restrict__ bq, const float* __restrict__ bk,
                     const float* __restrict__ bv)
{
    __shared__ uint32_t Xh[64 * 36], Xl[64 * 36];
    __shared__ uint32_t Wf[64 * 36];

    const int which = blockIdx.y;
    const float* __restrict__ x    = (which == 0) ? qin : (which == 1) ? kin : vin;
    const float* __restrict__ bias = (which == 0) ? bq  : (which == 1) ? bk  : bv;
    float* __restrict__ out        = (which == 0) ? g_qh : (which == 1) ? g_kh : g_vh;
    const uint32_t* __restrict__ wf = g_wf + which * 32768;

    const int tid  = threadIdx.x;
    const int warp = tid >> 5;
    const int lane = tid & 31;
    const int gid  = lane >> 2;
    const int tig  = lane & 3;
    const int row0 = blockIdx.x * 64;

    float acc[8][4] = {};

    for (int kb = 0; kb < 16; kb++) {
        __syncthreads();
        #pragma unroll
        for (int it = 0; it < 8; it++) {
            const int f = it * 128 + tid;
            const int r = f >> 4;
            const int c4 = (f & 15) << 2;
            float4 v = *(const float4*)(x + (size_t)(row0 + r) * DMODEL + kb * 64 + c4);
            uint32_t h0 = cvt_h2(v.x, v.y);
            uint32_t h1 = cvt_h2(v.z, v.w);
            uint32_t l0 = cvt_h2lo(make_float2(v.x, v.y), h0);
            uint32_t l1 = cvt_h2lo(make_float2(v.z, v.w), h1);
            *(uint2*)&Xh[r * 36 + (c4 >> 1)] = make_uint2(h0, h1);
            *(uint2*)&Xl[r * 36 + (c4 >> 1)] = make_uint2(l0, l1);
        }
        #pragma unroll
        for (int it = 0; it < 16; it++) {
            const int f = it * 128 + tid;
            const int n = f >> 5;
            const int k2 = f & 31;
            Wf[n * 36 + k2] = wf[n * 512 + kb * 32 + k2];
        }
        __syncthreads();

        #pragma unroll
        for (int ks = 0; ks < 4; ks++) {
            const int d2 = (ks << 3) + tig;
            const int ra = (warp << 4) + gid;
            uint32_t ah[4], al[4];
            ah[0] = Xh[ra * 36 + d2];        al[0] = Xl[ra * 36 + d2];
            ah[1] = Xh[(ra + 8) * 36 + d2];  al[1] = Xl[(ra + 8) * 36 + d2];
            ah[2] = Xh[ra * 36 + d2 + 4];    al[2] = Xl[ra * 36 + d2 + 4];
            ah[3] = Xh[(ra + 8) * 36 + d2 + 4]; al[3] = Xl[(ra + 8) * 36 + d2 + 4];
            #pragma unroll
            for (int nt = 0; nt < 8; nt++) {
                const int nr = (nt << 3) + gid;
                const uint32_t b0 = Wf[nr * 36 + d2], b1 = Wf[nr * 36 + d2 + 4];
                mma16816f16(acc[nt], ah, b0, b1);
                mma16816f16(acc[nt], al, b0, b1);
            }
        }
    }

    const int row = row0 + (warp << 4) + gid;
    #pragma unroll
    for (int nt = 0; nt < 8; nt++) {
        const int col = (nt << 3) + (tig << 1);
        const float b0 = bias[col], b1 = bias[col + 1];
        *(float2*)(out + (size_t)row * DH + col) =
            make_float2(acc[nt][0] + b0, acc[nt][1] + b1);
        *(float2*)(out + (size_t)(row + 8) * DH + col) =
            make_float2(acc[nt][2] + b0, acc[nt][3] + b1);
    }
}

// ---------------------------------------------------------------------------
// Flash attention, split-KV, fp16 MMAs, cp.async double-buffered K/V staging.
// 4 CTAs/SM (192KB smem, 16 warps) for latency hiding.
// ---------------------------------------------------------------------------
__global__ __launch_bounds__(128, 4)
void attn_kernel()
{
    __shared__ uint4 Ksm[2][64 * 12];   // [buf][key][e] (8 used of 12/row)
    __shared__ uint4 Vsm[2][64 * 12];   // [buf][d][e]

    const int tid  = threadIdx.x;
    const int warp = tid >> 5;
    const int lane = tid & 31;
    const int gid  = lane >> 2;
    const int tig  = lane & 3;

    const int bgid = (ATTN_BLOCKS - 1) - blockIdx.x;
    const int bb   = bgid / 288;
    const int r    = bgid - bb * 288;
    int a = 0;
    #pragma unroll
    for (int t = 1; t < 8; t++)
        if (4 * t * (t + 1) <= r) a = t;       // octave: qt in [8a, 8a+8)
    const int rr = r - 4 * a * (a + 1);
    const int qt = 8 * a + rr / (a + 1);
    const int ch = rr - (rr / (a + 1)) * (a + 1);

    const int q0  = qt * 64;
    const int kt0 = ch * 8;
    const int kt1 = min(kt0 + 7, qt);

    const float* __restrict__ qh = g_qh + (size_t)bb * SEQ * DH;
    const uint4* __restrict__ kp4 = g_kp4 + (size_t)bb * SEQ * 8;
    const uint4* __restrict__ vpb = g_vp4 + (size_t)bb * 64 * 512;

    // indices for this thread's staging slice (4 rows x 8-entry halves)
    const int srk = tid >> 3;          // 0..15 -> rows via +16 steps
    const int sc  = tid & 7;           // 0..7

    // prefetch first tile into buf 0
    {
        const int k0 = kt0 * 64;
        const uint4* vp4 = vpb + (size_t)kt0 * 512;
        #pragma unroll
        for (int it = 0; it < 4; it++) {
            const int rk = srk + it * 16;
            cpa16(&Ksm[0][rk * 12 + sc], &kp4[(size_t)(k0 + rk) * 8 + sc]);
            cpa16(&Vsm[0][rk * 12 + sc], &vp4[rk * 8 + sc]);
        }
        CPA_COMMIT();
    }

    // Q fragments as fp16, once (overlaps with the first prefetch)
    uint32_t qf[4][4];
    const int rowA = q0 + (warp << 4) + gid;
    const int rowB = rowA + 8;
    {
        #pragma unroll
        for (int ks = 0; ks < 4; ks++) {
            const float* pA = qh + (size_t)rowA * DH + (ks << 4) + (tig << 1);
            const float* pB = qh + (size_t)rowB * DH + (ks << 4) + (tig << 1);
            float2 f0 = *(const float2*)(pA);
            float2 f1 = *(const float2*)(pB);
            float2 f2 = *(const float2*)(pA + 8);
            float2 f3 = *(const float2*)(pB + 8);
            qf[ks][0] = cvt_h2(f0.x, f0.y);
            qf[ks][1] = cvt_h2(f1.x, f1.y);
            qf[ks][2] = cvt_h2(f2.x, f2.y);
            qf[ks][3] = cvt_h2(f3.x, f3.y);
        }
    }

    float o[8][4] = {};
    float mA = -3.0e38f, mB = -3.0e38f, lA = 0.0f, lB = 0.0f;

    for (int kt = kt0; kt <= kt1; kt++) {
        const int b = (kt - kt0) & 1;
        CPA_WAIT0();
        __syncthreads();   // buf b ready for all; buf b^1 free (last read in kt-2)

        // prefetch next tile into buf b^1 (overlaps compute below)
        if (kt < kt1) {
            const int k0n = (kt + 1) * 64;
            const uint4* vp4 = vpb + (size_t)(kt + 1) * 512;
            #pragma unroll
            for (int it = 0; it < 4; it++) {
                const int rk = srk + it * 16;
                cpa16(&Ksm[b ^ 1][rk * 12 + sc], &kp4[(size_t)(k0n + rk) * 8 + sc]);
                cpa16(&Vsm[b ^ 1][rk * 12 + sc], &vp4[rk * 8 + sc]);
            }
            CPA_COMMIT();
        }

        const int k0 = kt * 64;
        // S = Q K^T (fp16, 32 MMAs)
        float s[8][4] = {};
        #pragma unroll
        for (int nt = 0; nt < 8; nt++) {
            const int krow = ((nt << 3) + gid) * 12;
            uint4 ka = Ksm[b][krow + tig];        // ks=0 (x,y), ks=2 (z,w)
            uint4 kb = Ksm[b][krow + 4 + tig];    // ks=1 (x,y), ks=3 (z,w)
            mma16816f16(s[nt], qf[0], ka.x, ka.y);
            mma16816f16(s[nt], qf[1], kb.x, kb.y);
            mma16816f16(s[nt], qf[2], ka.z, ka.w);
            mma16816f16(s[nt], qf[3], kb.z, kb.w);
        }

        // causal mask on raw scores (diagonal tile only)
        if (kt == qt) {
            #pragma unroll
            for (int nt = 0; nt < 8; nt++) {
                const int cb = k0 + (nt << 3) + (tig << 1);
                if (cb     > rowA) s[nt][0] = -1.0e30f;
                if (cb + 1 > rowA) s[nt][1] = -1.0e30f;
                if (cb     > rowB) s[nt][2] = -1.0e30f;
                if (cb + 1 > rowB) s[nt][3] = -1.0e30f;
            }
        }

        // online softmax on raw scores; exp folds in the 1/8 scale (MUFU)
        float mxA = -3.0e38f, mxB = -3.0e38f;
        #pragma unroll
        for (int nt = 0; nt < 8; nt++) {
            mxA = fmaxf(mxA, fmaxf(s[nt][0], s[nt][1]));
            mxB = fmaxf(mxB, fmaxf(s[nt][2], s[nt][3]));
        }
        mxA = fmaxf(mxA, __shfl_xor_sync(0xffffffffu, mxA, 1));
        mxA = fmaxf(mxA, __shfl_xor_sync(0xffffffffu, mxA, 2));
        mxB = fmaxf(mxB, __shfl_xor_sync(0xffffffffu, mxB, 1));
        mxB = fmaxf(mxB, __shfl_xor_sync(0xffffffffu, mxB, 2));
        const float mnA = fmaxf(mA, mxA), mnB = fmaxf(mB, mxB);
        const float aA = exp8(mA - mnA), aB = exp8(mB - mnB);
        mA = mnA; mB = mnB;
        float sumA = 0.0f, sumB = 0.0f;
        #pragma unroll
        for (int nt = 0; nt < 8; nt++) {
            s[nt][0] = exp8(s[nt][0] - mnA);
            s[nt][1] = exp8(s[nt][1] - mnA);
            s[nt][2] = exp8(s[nt][2] - mnB);
            s[nt][3] = exp8(s[nt][3] - mnB);
            sumA += s[nt][0] + s[nt][1];
            sumB += s[nt][2] + s[nt][3];
        }
        lA = lA * aA + sumA;
        lB = lB * aB + sumB;
        #pragma unroll
        for (int nt = 0; nt < 8; nt++) {
            o[nt][0] *= aA; o[nt][1] *= aA;
            o[nt][2] *= aB; o[nt][3] *= aB;
        }

        // O += P V  (fp16, 32 MMAs)
        uint32_t pf[4][4];
        #pragma unroll
        for (int kk = 0; kk < 4; kk++) {
            pf[kk][0] = cvt_h2(s[2 * kk][0],     s[2 * kk][1]);
            pf[kk][1] = cvt_h2(s[2 * kk][2],     s[2 * kk][3]);
            pf[kk][2] = cvt_h2(s[2 * kk + 1][0], s[2 * kk + 1][1]);
            pf[kk][3] = cvt_h2(s[2 * kk + 1][2], s[2 * kk + 1][3]);
        }
        #pragma unroll
        for (int nt = 0; nt < 8; nt++) {
            const int drow = ((nt << 3) + gid) * 12;
            uint4 va = Vsm[b][drow + tig];        // kk=0 (x,y), kk=2 (z,w)
            uint4 vb = Vsm[b][drow + 4 + tig];    // kk=1 (x,y), kk=3 (z,w)
            mma16816f16(o[nt], pf[0], va.x, va.y);
            mma16816f16(o[nt], pf[1], vb.x, vb.y);
            mma16816f16(o[nt], pf[2], va.z, va.w);
            mma16816f16(o[nt], pf[3], vb.z, vb.w);
        }
    }

    // finalize partials
    lA += __shfl_xor_sync(0xffffffffu, lA, 1);
    lA += __shfl_xor_sync(0xffffffffu, lA, 2);
    lB += __shfl_xor_sync(0xffffffffu, lB, 1);
    lB += __shfl_xor_sync(0xffffffffu, lB, 2);

    const int growA = bb * SEQ + rowA;
    const int growB = bb * SEQ + rowB;
    #pragma unroll
    for (int nt = 0; nt < 8; nt++) {
        const int col = (nt << 3) + (tig << 1);
        *(float2*)&g_po[ch][(size_t)growA * DH + col] = make_float2(o[nt][0], o[nt][1]);
        *(float2*)&g_po[ch][(size_t)growB * DH + col] = make_float2(o[nt][2], o[nt][3]);
    }
    if (tig == 0) {
        g_pm[ch][growA] = mA * 0.125f; g_pl[ch][growA] = lA;
        g_pm[ch][growB] = mB * 0.125f; g_pl[ch][growB] = lB;
    }
}

// ---------------------------------------------------------------------------
__global__ __launch_bounds__(256)
void merge_kernel(float* __restrict__ out)
{
    const int t = blockIdx.x * 256 + threadIdx.x;
    const int row = t >> 4;
    const int cg  = (t & 15) << 2;
    const int q   = row & (SEQ - 1);
    const int nc  = ((q >> 6) >> 3) + 1;     // 512-key chunks

    float mstar = -3.0e38f;
    #pragma unroll 4
    for (int c = 0; c < nc; c++)
        mstar = fmaxf(mstar, g_pm[c][row]);

    float L = 0.0f;
    float4 acc = make_float4(0.f, 0.f, 0.f, 0.f);
    #pragma unroll 4
    for (int c = 0; c < nc; c++) {
        const float wgt = __expf(g_pm[c][row] - mstar);
        L += wgt * g_pl[c][row];
        float4 ov = *(const float4*)&g_po[c][(size_t)row * DH + cg];
        acc.x += wgt * ov.x; acc.y += wgt * ov.y;
        acc.z += wgt * ov.z; acc.w += wgt * ov.w;
    }
    const float inv = 1.0f / L;
    *(float4*)(out + (size_t)row * DH + cg) =
        make_float4(acc.x * inv, acc.y * inv, acc.z * inv, acc.w * inv);
}

// ---------------------------------------------------------------------------
extern "C" void kernel_launch(void* const* d_in, const int* in_sizes, int n_in,
                              void* d_out, int out_size)
{
    (void)in_sizes; (void)n_in; (void)out_size;
    const float* q  = (const float*)d_in[0];
    const float* k  = (const float*)d_in[1];
    const float* v  = (const float*)d_in[2];
    const float* wq = (const float*)d_in[3];
    const float* bq = (const float*)d_in[4];
    const float* wk = (const float*)d_in[5];
    const float* bk = (const float*)d_in[6];
    const float* wv = (const float*)d_in[7];
    const float* bv = (const float*)d_in[8];
    float* out = (float*)d_out;

    // Ensure 192KB smem/SM is available for 4 CTAs of attn (one-time, idempotent)
    static bool configured = false;
    if (!configured) {
        cudaFuncSetAttribute(attn_kernel,
                             cudaFuncAttributePreferredSharedMemoryCarveout, 100);
        configured = true;
    }

    wconv_kernel<<<384, 256>>>(wq, wk, wv);
    dim3 pgrid(BATCH * SEQ / 64, 3);   // (256, 3)
    proj_mma_kernel<<<pgrid, 128>>>(q, k, v, bq, bk, bv);
    kpack_kernel<<<BATCH * SEQ * 8 / 256, 256>>>();
    vpack_kernel<<<BATCH * SEQ / 64, 256>>>();
    attn_kernel<<<ATTN_BLOCKS, 128>>>();
    merge_kernel<<<BATCH * SEQ * 16 / 256, 256>>>(out);
}